// round 1
// baseline (speedup 1.0000x reference)
#include <cuda_runtime.h>
#include <math.h>

#define NB 4
#define NH 12
#define SL 2048
#define DK 64
#define DM 768
#define BH (NB*NH)

// Head-split scratch: [B*H, S, DK] each. Static device globals (no allocation).
__device__ float g_q[BH * SL * DK];
__device__ float g_k[BH * SL * DK];
__device__ float g_v[BH * SL * DK];

// ---------------------------------------------------------------------------
// QKV projection: Y = X @ W + b, written in head-split layout.
// grid = (M/128 = 64, N/64 = 12 heads, 3 = Q/K/V), 256 threads.
// 8x4 micro-tile per thread; rows = ty + 16*i, cols = tx + 16*j (conflict-free).
// ---------------------------------------------------------------------------
__global__ __launch_bounds__(256) void qkv_proj_kernel(
    const float* __restrict__ q_in, const float* __restrict__ k_in,
    const float* __restrict__ v_in,
    const float* __restrict__ Wq, const float* __restrict__ Wk,
    const float* __restrict__ Wv,
    const float* __restrict__ bq, const float* __restrict__ bk,
    const float* __restrict__ bv)
{
    __shared__ float Xs[128][17];
    __shared__ float Ws[16][65];

    const int tid = threadIdx.x;
    const int ty = tid >> 4, tx = tid & 15;
    const int m0 = blockIdx.x * 128;
    const int h  = blockIdx.y;
    const int n0 = h * DK;
    const int sel = blockIdx.z;

    const float* X    = (sel == 0) ? q_in : (sel == 1) ? k_in : v_in;
    const float* W    = (sel == 0) ? Wq   : (sel == 1) ? Wk   : Wv;
    const float* bias = (sel == 0) ? bq   : (sel == 1) ? bk   : bv;
    float* dst        = (sel == 0) ? g_q  : (sel == 1) ? g_k  : g_v;

    float acc[8][4];
#pragma unroll
    for (int i = 0; i < 8; i++)
#pragma unroll
        for (int j = 0; j < 4; j++) acc[i][j] = 0.f;

    for (int k0 = 0; k0 < DM; k0 += 16) {
        // Load X tile 128x16 (512 float4, 2 per thread)
#pragma unroll
        for (int r = 0; r < 2; r++) {
            int idx = tid + r * 256;
            int row = idx >> 2;
            int c4  = (idx & 3) * 4;
            float4 v = *(const float4*)(X + (size_t)(m0 + row) * DM + k0 + c4);
            Xs[row][c4 + 0] = v.x; Xs[row][c4 + 1] = v.y;
            Xs[row][c4 + 2] = v.z; Xs[row][c4 + 3] = v.w;
        }
        // Load W tile 16x64 (256 float4, 1 per thread)
        {
            int row = tid >> 4;
            int c4  = (tid & 15) * 4;
            float4 v = *(const float4*)(W + (size_t)(k0 + row) * DM + n0 + c4);
            Ws[row][c4 + 0] = v.x; Ws[row][c4 + 1] = v.y;
            Ws[row][c4 + 2] = v.z; Ws[row][c4 + 3] = v.w;
        }
        __syncthreads();

#pragma unroll
        for (int kk = 0; kk < 16; kk++) {
            float a[8], b[4];
#pragma unroll
            for (int i = 0; i < 8; i++) a[i] = Xs[ty + 16 * i][kk];
#pragma unroll
            for (int j = 0; j < 4; j++) b[j] = Ws[kk][tx + 16 * j];
#pragma unroll
            for (int i = 0; i < 8; i++)
#pragma unroll
                for (int j = 0; j < 4; j++) acc[i][j] += a[i] * b[j];
        }
        __syncthreads();
    }

    float bb[4];
#pragma unroll
    for (int j = 0; j < 4; j++) bb[j] = bias[n0 + tx + 16 * j];

#pragma unroll
    for (int i = 0; i < 8; i++) {
        int m    = m0 + ty + 16 * i;
        int bidx = m >> 11;          // / SL
        int s    = m & (SL - 1);
        float* o = dst + (((size_t)bidx * NH + h) * SL + s) * DK;
#pragma unroll
        for (int j = 0; j < 4; j++) o[tx + 16 * j] = acc[i][j] + bb[j];
    }
}

// ---------------------------------------------------------------------------
// Flash attention, fp32. grid = (S/64 = 32, B*H = 48), 256 threads.
// Per block: 64 query rows, loop over 32 K/V tiles of 64 rows.
// Thread (ty,tx): rows ty+16i, cols tx+16j, i,j in 0..3 (conflict-free LDS).
// ---------------------------------------------------------------------------
__global__ __launch_bounds__(256) void attn_kernel(float* __restrict__ out)
{
    extern __shared__ float sm[];
    float* Qs = sm;                 // [64][65]
    float* Ks = sm + 64 * 65;       // [64][65]
    float* Vs = sm + 2 * 64 * 65;   // [64][65]
    float* Ps = sm + 3 * 64 * 65;   // [64][65]

    const int tid = threadIdx.x;
    const int ty = tid >> 4, tx = tid & 15;
    const int bh = blockIdx.y;
    const int q0 = blockIdx.x * 64;

    const float* Qb = g_q + (size_t)bh * SL * DK;
    const float* Kb = g_k + (size_t)bh * SL * DK;
    const float* Vb = g_v + (size_t)bh * SL * DK;

    // Load Q tile 64x64 (1024 float4, 4 per thread)
#pragma unroll
    for (int it = 0; it < 4; it++) {
        int idx = tid + it * 256;
        int row = idx >> 4;
        int c4  = (idx & 15) * 4;
        float4 v = *(const float4*)(Qb + (size_t)(q0 + row) * DK + c4);
        Qs[row * 65 + c4 + 0] = v.x; Qs[row * 65 + c4 + 1] = v.y;
        Qs[row * 65 + c4 + 2] = v.z; Qs[row * 65 + c4 + 3] = v.w;
    }

    float m_i[4], l_i[4], ctx[4][4];
#pragma unroll
    for (int i = 0; i < 4; i++) {
        m_i[i] = -1e30f;
        l_i[i] = 0.f;
#pragma unroll
        for (int j = 0; j < 4; j++) ctx[i][j] = 0.f;
    }

    for (int n0 = 0; n0 < SL; n0 += 64) {
        // Load K and V tiles (each 64x64)
#pragma unroll
        for (int it = 0; it < 4; it++) {
            int idx = tid + it * 256;
            int row = idx >> 4;
            int c4  = (idx & 15) * 4;
            float4 kv = *(const float4*)(Kb + (size_t)(n0 + row) * DK + c4);
            Ks[row * 65 + c4 + 0] = kv.x; Ks[row * 65 + c4 + 1] = kv.y;
            Ks[row * 65 + c4 + 2] = kv.z; Ks[row * 65 + c4 + 3] = kv.w;
            float4 vv = *(const float4*)(Vb + (size_t)(n0 + row) * DK + c4);
            Vs[row * 65 + c4 + 0] = vv.x; Vs[row * 65 + c4 + 1] = vv.y;
            Vs[row * 65 + c4 + 2] = vv.z; Vs[row * 65 + c4 + 3] = vv.w;
        }
        __syncthreads();

        // S = Q K^T for this tile
        float s[4][4];
#pragma unroll
        for (int i = 0; i < 4; i++)
#pragma unroll
            for (int j = 0; j < 4; j++) s[i][j] = 0.f;

#pragma unroll 16
        for (int k = 0; k < 64; k++) {
            float a[4], b[4];
#pragma unroll
            for (int i = 0; i < 4; i++) a[i] = Qs[(ty + 16 * i) * 65 + k];
#pragma unroll
            for (int j = 0; j < 4; j++) b[j] = Ks[(tx + 16 * j) * 65 + k];
#pragma unroll
            for (int i = 0; i < 4; i++)
#pragma unroll
                for (int j = 0; j < 4; j++) s[i][j] += a[i] * b[j];
        }

        // Online softmax update (rows owned by 16-lane half-warp groups)
#pragma unroll
        for (int i = 0; i < 4; i++) {
            float mx = -1e30f;
#pragma unroll
            for (int j = 0; j < 4; j++) {
                s[i][j] *= 0.125f;               // 1/sqrt(64)
                mx = fmaxf(mx, s[i][j]);
            }
#pragma unroll
            for (int off = 8; off > 0; off >>= 1)
                mx = fmaxf(mx, __shfl_xor_sync(0xffffffffu, mx, off, 16));

            float mn = fmaxf(m_i[i], mx);
            float al = __expf(m_i[i] - mn);
            float rs = 0.f;
#pragma unroll
            for (int j = 0; j < 4; j++) {
                float p = __expf(s[i][j] - mn);
                s[i][j] = p;
                rs += p;
            }
#pragma unroll
            for (int off = 8; off > 0; off >>= 1)
                rs += __shfl_xor_sync(0xffffffffu, rs, off, 16);

            l_i[i] = l_i[i] * al + rs;
            m_i[i] = mn;
#pragma unroll
            for (int j = 0; j < 4; j++) {
                ctx[i][j] *= al;
                Ps[(ty + 16 * i) * 65 + tx + 16 * j] = s[i][j];
            }
        }
        __syncthreads();

        // ctx += P V
#pragma unroll 16
        for (int n = 0; n < 64; n++) {
            float p[4], b[4];
#pragma unroll
            for (int i = 0; i < 4; i++) p[i] = Ps[(ty + 16 * i) * 65 + n];
#pragma unroll
            for (int j = 0; j < 4; j++) b[j] = Vs[n * 65 + tx + 16 * j];
#pragma unroll
            for (int i = 0; i < 4; i++)
#pragma unroll
                for (int j = 0; j < 4; j++) ctx[i][j] += p[i] * b[j];
        }
        __syncthreads();   // protect Ks/Vs/Ps before next tile load
    }

    // Epilogue: normalize and store to [B, S, H*DK]
    const int b_idx = bh / NH;
    const int h     = bh % NH;
#pragma unroll
    for (int i = 0; i < 4; i++) {
        float inv = 1.0f / l_i[i];
        int srow = q0 + ty + 16 * i;
        float* o = out + ((size_t)b_idx * SL + srow) * DM + h * DK;
#pragma unroll
        for (int j = 0; j < 4; j++) o[tx + 16 * j] = ctx[i][j] * inv;
    }
}

// ---------------------------------------------------------------------------
extern "C" void kernel_launch(void* const* d_in, const int* in_sizes, int n_in,
                              void* d_out, int out_size)
{
    const float* query = (const float*)d_in[0];
    const float* key_  = (const float*)d_in[1];
    const float* value = (const float*)d_in[2];
    const float* W_Q   = (const float*)d_in[3];
    const float* b_Q   = (const float*)d_in[4];
    const float* W_K   = (const float*)d_in[5];
    const float* b_K   = (const float*)d_in[6];
    const float* W_V   = (const float*)d_in[7];
    const float* b_V   = (const float*)d_in[8];
    float* out = (float*)d_out;

    dim3 gp((NB * SL) / 128, NH, 3);
    qkv_proj_kernel<<<gp, 256>>>(query, key_, value, W_Q, W_K, W_V, b_Q, b_K, b_V);

    const int smem = 4 * 64 * 65 * (int)sizeof(float);   // 66560 bytes
    cudaFuncSetAttribute(attn_kernel,
                         cudaFuncAttributeMaxDynamicSharedMemorySize, smem);
    dim3 ga(SL / 64, BH);
    attn_kernel<<<ga, 256, smem>>>(out);
}

// round 2
// speedup vs baseline: 1.0856x; 1.0856x over previous
#include <cuda_runtime.h>
#include <math.h>

#define NB 4
#define NH 12
#define SL 2048
#define DK 64
#define DM 768
#define BH (NB*NH)

// Head-split scratch: [B*H, S, DK] each. Static device globals (no allocation).
__device__ float g_q[BH * SL * DK];
__device__ float g_k[BH * SL * DK];
__device__ float g_v[BH * SL * DK];

// ---------------------------------------------------------------------------
// QKV projection: Y = X @ W + b, head-split output.
// grid = (8192/128 = 64, 768/128 = 6, 3), 256 threads, 8x8 micro-tile.
// rows = ty + 16*i, cols = tx + 16*j  (i,j < 8)  -> conflict-free LDS.
// ---------------------------------------------------------------------------
__global__ __launch_bounds__(256) void qkv_proj_kernel(
    const float* __restrict__ q_in, const float* __restrict__ k_in,
    const float* __restrict__ v_in,
    const float* __restrict__ Wq, const float* __restrict__ Wk,
    const float* __restrict__ Wv,
    const float* __restrict__ bq, const float* __restrict__ bk,
    const float* __restrict__ bv)
{
    __shared__ float Xs[128][17];
    __shared__ float Ws[16][132];

    const int tid = threadIdx.x;
    const int ty = tid >> 4, tx = tid & 15;
    const int m0 = blockIdx.x * 128;
    const int n0 = blockIdx.y * 128;
    const int sel = blockIdx.z;

    const float* X    = (sel == 0) ? q_in : (sel == 1) ? k_in : v_in;
    const float* W    = (sel == 0) ? Wq   : (sel == 1) ? Wk   : Wv;
    const float* bias = (sel == 0) ? bq   : (sel == 1) ? bk   : bv;
    float* dst        = (sel == 0) ? g_q  : (sel == 1) ? g_k  : g_v;

    float acc[8][8];
#pragma unroll
    for (int i = 0; i < 8; i++)
#pragma unroll
        for (int j = 0; j < 8; j++) acc[i][j] = 0.f;

    for (int k0 = 0; k0 < DM; k0 += 16) {
        // X tile 128x16 = 512 float4, 2 per thread
#pragma unroll
        for (int r = 0; r < 2; r++) {
            int idx = tid + r * 256;
            int row = idx >> 2;
            int c4  = (idx & 3) * 4;
            float4 v = *(const float4*)(X + (size_t)(m0 + row) * DM + k0 + c4);
            Xs[row][c4 + 0] = v.x; Xs[row][c4 + 1] = v.y;
            Xs[row][c4 + 2] = v.z; Xs[row][c4 + 3] = v.w;
        }
        // W tile 16x128 = 512 float4, 2 per thread
#pragma unroll
        for (int r = 0; r < 2; r++) {
            int idx = tid + r * 256;
            int row = idx >> 5;
            int c4  = (idx & 31) * 4;
            float4 v = *(const float4*)(W + (size_t)(k0 + row) * DM + n0 + c4);
            Ws[row][c4 + 0] = v.x; Ws[row][c4 + 1] = v.y;
            Ws[row][c4 + 2] = v.z; Ws[row][c4 + 3] = v.w;
        }
        __syncthreads();

#pragma unroll
        for (int kk = 0; kk < 16; kk++) {
            float a[8], b[8];
#pragma unroll
            for (int i = 0; i < 8; i++) a[i] = Xs[ty + 16 * i][kk];
#pragma unroll
            for (int j = 0; j < 8; j++) b[j] = Ws[kk][tx + 16 * j];
#pragma unroll
            for (int i = 0; i < 8; i++)
#pragma unroll
                for (int j = 0; j < 8; j++) acc[i][j] += a[i] * b[j];
        }
        __syncthreads();
    }

    float bb[8];
#pragma unroll
    for (int j = 0; j < 8; j++) bb[j] = bias[n0 + tx + 16 * j];

#pragma unroll
    for (int i = 0; i < 8; i++) {
        int m    = m0 + ty + 16 * i;
        int bidx = m >> 11;          // / SL
        int s    = m & (SL - 1);
#pragma unroll
        for (int j = 0; j < 8; j++) {
            int n = n0 + tx + 16 * j;
            int h = n >> 6;
            int c = n & 63;
            dst[(((size_t)bidx * NH + h) * SL + s) * DK + c] = acc[i][j] + bb[j];
        }
    }
}

// ---------------------------------------------------------------------------
// Flash attention, fp32. grid = (S/128 = 16, B*H = 48), 256 threads.
// Br=128 q-rows per block, Bc=128 k-cols per tile, 16 tiles.
// QK^T: 8x8 micro-tile (rows ty+16i, cols tx+16j).
// PV  : 8x4 micro-tile with float2-paired P reads.
// ---------------------------------------------------------------------------
#define QST 66     // Q/K/V smem row stride (conflict-free: 66 % 32 == 2)
#define PST 132    // P smem row stride

__global__ __launch_bounds__(256) void attn_kernel(float* __restrict__ out)
{
    extern __shared__ float sm[];
    float* Qs = sm;                    // [128][QST]
    float* Ks = sm + 128 * QST;        // [128][QST]
    float* Vs = sm + 2 * 128 * QST;    // [128][QST]
    float* Ps = sm + 3 * 128 * QST;    // [128][PST]

    const int tid = threadIdx.x;
    const int ty = tid >> 4, tx = tid & 15;
    const int bh = blockIdx.y;
    const int q0 = blockIdx.x * 128;

    const float* Qb = g_q + (size_t)bh * SL * DK;
    const float* Kb = g_k + (size_t)bh * SL * DK;
    const float* Vb = g_v + (size_t)bh * SL * DK;

    // Load Q tile 128x64 = 2048 float4, 8 per thread
#pragma unroll
    for (int it = 0; it < 8; it++) {
        int idx = tid + it * 256;
        int row = idx >> 4;
        int c4  = (idx & 15) * 4;
        float4 v = *(const float4*)(Qb + (size_t)(q0 + row) * DK + c4);
        Qs[row * QST + c4 + 0] = v.x; Qs[row * QST + c4 + 1] = v.y;
        Qs[row * QST + c4 + 2] = v.z; Qs[row * QST + c4 + 3] = v.w;
    }

    float m_i[8], l_i[8], ctx[8][4];
#pragma unroll
    for (int i = 0; i < 8; i++) {
        m_i[i] = -1e30f;
        l_i[i] = 0.f;
#pragma unroll
        for (int j = 0; j < 4; j++) ctx[i][j] = 0.f;
    }

    for (int n0 = 0; n0 < SL; n0 += 128) {
        // Load K and V tiles (each 128x64 = 2048 float4, 8 per thread each)
#pragma unroll
        for (int it = 0; it < 8; it++) {
            int idx = tid + it * 256;
            int row = idx >> 4;
            int c4  = (idx & 15) * 4;
            float4 kv = *(const float4*)(Kb + (size_t)(n0 + row) * DK + c4);
            Ks[row * QST + c4 + 0] = kv.x; Ks[row * QST + c4 + 1] = kv.y;
            Ks[row * QST + c4 + 2] = kv.z; Ks[row * QST + c4 + 3] = kv.w;
            float4 vv = *(const float4*)(Vb + (size_t)(n0 + row) * DK + c4);
            Vs[row * QST + c4 + 0] = vv.x; Vs[row * QST + c4 + 1] = vv.y;
            Vs[row * QST + c4 + 2] = vv.z; Vs[row * QST + c4 + 3] = vv.w;
        }
        __syncthreads();

        // S = Q K^T (128x128 tile, 8x8 per thread)
        float s[8][8];
#pragma unroll
        for (int i = 0; i < 8; i++)
#pragma unroll
            for (int j = 0; j < 8; j++) s[i][j] = 0.f;

#pragma unroll 8
        for (int k = 0; k < 64; k++) {
            float a[8], b[8];
#pragma unroll
            for (int i = 0; i < 8; i++) a[i] = Qs[(ty + 16 * i) * QST + k];
#pragma unroll
            for (int j = 0; j < 8; j++) b[j] = Ks[(tx + 16 * j) * QST + k];
#pragma unroll
            for (int i = 0; i < 8; i++)
#pragma unroll
                for (int j = 0; j < 8; j++) s[i][j] += a[i] * b[j];
        }

        // Online softmax (rows owned by 16-lane groups)
#pragma unroll
        for (int i = 0; i < 8; i++) {
            float mx = -1e30f;
#pragma unroll
            for (int j = 0; j < 8; j++) {
                s[i][j] *= 0.125f;               // 1/sqrt(64)
                mx = fmaxf(mx, s[i][j]);
            }
#pragma unroll
            for (int off = 8; off > 0; off >>= 1)
                mx = fmaxf(mx, __shfl_xor_sync(0xffffffffu, mx, off, 16));

            float mn = fmaxf(m_i[i], mx);
            float al = __expf(m_i[i] - mn);
            float rs = 0.f;
#pragma unroll
            for (int j = 0; j < 8; j++) {
                float p = __expf(s[i][j] - mn);
                s[i][j] = p;
                rs += p;
            }
#pragma unroll
            for (int off = 8; off > 0; off >>= 1)
                rs += __shfl_xor_sync(0xffffffffu, rs, off, 16);

            l_i[i] = l_i[i] * al + rs;
            m_i[i] = mn;
#pragma unroll
            for (int j = 0; j < 4; j++) ctx[i][j] *= al;
#pragma unroll
            for (int j = 0; j < 8; j++)
                Ps[(ty + 16 * i) * PST + tx + 16 * j] = s[i][j];
        }
        __syncthreads();

        // ctx += P V   (P rows via float2 pairs over n)
#pragma unroll 8
        for (int n = 0; n < 128; n += 2) {
            float2 p2[8];
            float v0[4], v1[4];
#pragma unroll
            for (int i = 0; i < 8; i++)
                p2[i] = *(const float2*)(Ps + (ty + 16 * i) * PST + n);
#pragma unroll
            for (int j = 0; j < 4; j++) {
                v0[j] = Vs[n * QST + tx + 16 * j];
                v1[j] = Vs[(n + 1) * QST + tx + 16 * j];
            }
#pragma unroll
            for (int i = 0; i < 8; i++)
#pragma unroll
                for (int j = 0; j < 4; j++)
                    ctx[i][j] += p2[i].x * v0[j] + p2[i].y * v1[j];
        }
        __syncthreads();   // protect Ks/Vs/Ps before next tile load
    }

    // Epilogue: normalize and store to [B, S, H*DK]
    const int b_idx = bh / NH;
    const int h     = bh % NH;
#pragma unroll
    for (int i = 0; i < 8; i++) {
        float inv = 1.0f / l_i[i];
        int srow = q0 + ty + 16 * i;
        float* o = out + ((size_t)b_idx * SL + srow) * DM + h * DK;
#pragma unroll
        for (int j = 0; j < 4; j++) o[tx + 16 * j] = ctx[i][j] * inv;
    }
}

// ---------------------------------------------------------------------------
extern "C" void kernel_launch(void* const* d_in, const int* in_sizes, int n_in,
                              void* d_out, int out_size)
{
    const float* query = (const float*)d_in[0];
    const float* key_  = (const float*)d_in[1];
    const float* value = (const float*)d_in[2];
    const float* W_Q   = (const float*)d_in[3];
    const float* b_Q   = (const float*)d_in[4];
    const float* W_K   = (const float*)d_in[5];
    const float* b_K   = (const float*)d_in[6];
    const float* W_V   = (const float*)d_in[7];
    const float* b_V   = (const float*)d_in[8];
    float* out = (float*)d_out;

    dim3 gp((NB * SL) / 128, DM / 128, 3);
    qkv_proj_kernel<<<gp, 256>>>(query, key_, value, W_Q, W_K, W_V, b_Q, b_K, b_V);

    const int smem = (3 * 128 * QST + 128 * PST) * (int)sizeof(float); // 168960
    cudaFuncSetAttribute(attn_kernel,
                         cudaFuncAttributeMaxDynamicSharedMemorySize, smem);
    dim3 ga(SL / 128, BH);
    attn_kernel<<<ga, 256, smem>>>(out);
}

// round 5
// speedup vs baseline: 2.3254x; 2.1421x over previous
#include <cuda_runtime.h>
#include <cuda_bf16.h>
#include <math.h>
#include <stdint.h>

#define NB 4
#define NH 12
#define SL 2048
#define DK 64
#define DM 768
#define BH (NB*NH)
#define MROWS (NB*SL)          // 8192
#define ST 72                  // smem row stride in bf16 elems (144B: conflict-free frags)

// ---------------------------------------------------------------------------
// Device scratch (static; no allocation)
// ---------------------------------------------------------------------------
__device__ __nv_bfloat16 g_xh[3][(size_t)MROWS * DM];
__device__ __nv_bfloat16 g_xl[3][(size_t)MROWS * DM];
__device__ __nv_bfloat16 g_wth[3][DM * DM];   // W^T (n,k), hi
__device__ __nv_bfloat16 g_wtl[3][DM * DM];   // W^T (n,k), lo

__device__ __nv_bfloat16 g_qh[(size_t)BH * SL * DK];
__device__ __nv_bfloat16 g_ql[(size_t)BH * SL * DK];
__device__ __nv_bfloat16 g_kh[(size_t)BH * SL * DK];
__device__ __nv_bfloat16 g_kl[(size_t)BH * SL * DK];
__device__ __nv_bfloat16 g_vh[(size_t)BH * SL * DK];
__device__ __nv_bfloat16 g_vl[(size_t)BH * SL * DK];

// ---------------------------------------------------------------------------
// Helpers
// ---------------------------------------------------------------------------
__device__ __forceinline__ void mma16816(float* c, const uint32_t* a,
                                         const uint32_t* b) {
    asm volatile(
        "mma.sync.aligned.m16n8k16.row.col.f32.bf16.bf16.f32 "
        "{%0,%1,%2,%3}, {%4,%5,%6,%7}, {%8,%9}, {%0,%1,%2,%3};\n"
        : "+f"(c[0]), "+f"(c[1]), "+f"(c[2]), "+f"(c[3])
        : "r"(a[0]), "r"(a[1]), "r"(a[2]), "r"(a[3]), "r"(b[0]), "r"(b[1]));
}

// FFMA-pipe exp2 (no MUFU): degree-6 poly on [0,1) + exponent-bit scaling.
__device__ __forceinline__ float exp2a(float x) {
    x = fmaxf(x, -80.f);
    float xi = floorf(x);
    float f = x - xi;
    float p = 1.53533e-4f;
    p = fmaf(p, f, 1.33989e-3f);
    p = fmaf(p, f, 9.61844e-3f);
    p = fmaf(p, f, 5.55033e-2f);
    p = fmaf(p, f, 2.40226e-1f);
    p = fmaf(p, f, 6.93147e-1f);
    p = fmaf(p, f, 1.0f);
    return p * __int_as_float(((int)xi + 127) << 23);
}

__device__ __forceinline__ void split2(float a, float b, uint32_t& h, uint32_t& l) {
    __nv_bfloat162 H = __floats2bfloat162_rn(a, b);
    float ra = a - __bfloat162float(H.x);
    float rb = b - __bfloat162float(H.y);
    __nv_bfloat162 L = __floats2bfloat162_rn(ra, rb);
    h = *(uint32_t*)&H;
    l = *(uint32_t*)&L;
}

// ---------------------------------------------------------------------------
// Conversion: X -> (hi, lo) bf16 split.
// ---------------------------------------------------------------------------
__global__ __launch_bounds__(256) void convert_x_kernel(
    const float* __restrict__ q, const float* __restrict__ k,
    const float* __restrict__ v)
{
    const int sel = blockIdx.y;
    const float* src = (sel == 0) ? q : (sel == 1) ? k : v;
    __nv_bfloat16* xh = g_xh[sel];
    __nv_bfloat16* xl = g_xl[sel];

    size_t idx = (size_t)blockIdx.x * blockDim.x + threadIdx.x;  // float4 index
    float4 x = ((const float4*)src)[idx];
    float vv[4] = {x.x, x.y, x.z, x.w};
    uint32_t h[2], l[2];
    split2(vv[0], vv[1], h[0], l[0]);
    split2(vv[2], vv[3], h[1], l[1]);
    ((uint32_t*)xh)[idx * 2 + 0] = h[0];
    ((uint32_t*)xh)[idx * 2 + 1] = h[1];
    ((uint32_t*)xl)[idx * 2 + 0] = l[0];
    ((uint32_t*)xl)[idx * 2 + 1] = l[1];
}

// ---------------------------------------------------------------------------
// Conversion: W[k][n] -> W^T[n][k] (hi, lo) bf16.
// ---------------------------------------------------------------------------
__global__ void convert_w_kernel(const float* __restrict__ Wq,
                                 const float* __restrict__ Wk,
                                 const float* __restrict__ Wv)
{
    __shared__ float t[32][33];
    const int sel = blockIdx.z;
    const float* W = (sel == 0) ? Wq : (sel == 1) ? Wk : Wv;
    const int k0 = blockIdx.x * 32;
    const int n0 = blockIdx.y * 32;
    const int tx = threadIdx.x, ty = threadIdx.y;

#pragma unroll
    for (int r = 0; r < 4; r++)
        t[ty + 8 * r][tx] = W[(size_t)(k0 + ty + 8 * r) * DM + n0 + tx];
    __syncthreads();

#pragma unroll
    for (int r = 0; r < 4; r++) {
        float v = t[tx][ty + 8 * r];
        __nv_bfloat16 h = __float2bfloat16_rn(v);
        __nv_bfloat16 l = __float2bfloat16_rn(v - __bfloat162float(h));
        size_t o = (size_t)(n0 + ty + 8 * r) * DM + k0 + tx;
        g_wth[sel][o] = h;
        g_wtl[sel][o] = l;
    }
}

// ---------------------------------------------------------------------------
// QKV projection via mma.sync bf16 split-precision.
// grid (64, 6, 3), 256 thr (8 warps: 2x4, warp tile 64x32).
// Outputs head-split bf16 hi/lo.
// ---------------------------------------------------------------------------
__global__ __launch_bounds__(256) void qkv_proj_mma_kernel(
    const float* __restrict__ bq, const float* __restrict__ bk,
    const float* __restrict__ bv)
{
    extern __shared__ __nv_bfloat16 sm[];
    __nv_bfloat16* Xh = sm;                 // [128][ST]
    __nv_bfloat16* Xl = sm + 128 * ST;
    __nv_bfloat16* Wh = sm + 2 * 128 * ST;
    __nv_bfloat16* Wl = sm + 3 * 128 * ST;

    const int tid  = threadIdx.x;
    const int lane = tid & 31, wid = tid >> 5;
    const int wm = wid >> 2, wn = wid & 3;       // warp at (wm*64, wn*32)
    const int m0 = blockIdx.x * 128;
    const int n0 = blockIdx.y * 128;
    const int sel = blockIdx.z;

    const __nv_bfloat16* Agh = g_xh[sel];
    const __nv_bfloat16* Agl = g_xl[sel];
    const __nv_bfloat16* Bgh = g_wth[sel];
    const __nv_bfloat16* Bgl = g_wtl[sel];
    const float* bias = (sel == 0) ? bq : (sel == 1) ? bk : bv;
    __nv_bfloat16* dh = (sel == 0) ? g_qh : (sel == 1) ? g_kh : g_vh;
    __nv_bfloat16* dl = (sel == 0) ? g_ql : (sel == 1) ? g_kl : g_vl;

    float acc[4][4][4];
#pragma unroll
    for (int i = 0; i < 4; i++)
#pragma unroll
        for (int j = 0; j < 4; j++)
#pragma unroll
            for (int q = 0; q < 4; q++) acc[i][j][q] = 0.f;

    for (int ch = 0; ch < DM / 64; ch++) {
        const int k0 = ch * 64;
        // fill 4 tiles: 128 rows x 64 bf16 = 1024 float4 each, 4/thread
#pragma unroll
        for (int r = 0; r < 4; r++) {
            int idx = tid + r * 256;
            int row = idx >> 3;
            int c8  = (idx & 7) * 8;
            *(float4*)(Xh + row * ST + c8) =
                *(const float4*)(Agh + (size_t)(m0 + row) * DM + k0 + c8);
            *(float4*)(Xl + row * ST + c8) =
                *(const float4*)(Agl + (size_t)(m0 + row) * DM + k0 + c8);
            *(float4*)(Wh + row * ST + c8) =
                *(const float4*)(Bgh + (size_t)(n0 + row) * DM + k0 + c8);
            *(float4*)(Wl + row * ST + c8) =
                *(const float4*)(Bgl + (size_t)(n0 + row) * DM + k0 + c8);
        }
        __syncthreads();

#pragma unroll
        for (int pass = 0; pass < 3; pass++) {
            const __nv_bfloat16* As = (pass == 1) ? Xl : Xh;
            const __nv_bfloat16* Bs = (pass == 2) ? Wl : Wh;
#pragma unroll
            for (int ks = 0; ks < 4; ks++) {
                const int kb = ks * 16 + (lane & 3) * 2;
                uint32_t a[4][4], b[4][2];
#pragma unroll
                for (int i = 0; i < 4; i++) {
                    const __nv_bfloat16* ap =
                        As + (wm * 64 + 16 * i + (lane >> 2)) * ST + kb;
                    a[i][0] = *(const uint32_t*)ap;
                    a[i][1] = *(const uint32_t*)(ap + 8 * ST);
                    a[i][2] = *(const uint32_t*)(ap + 8);
                    a[i][3] = *(const uint32_t*)(ap + 8 * ST + 8);
                }
#pragma unroll
                for (int j = 0; j < 4; j++) {
                    const __nv_bfloat16* bp =
                        Bs + (wn * 32 + 8 * j + (lane >> 2)) * ST + kb;
                    b[j][0] = *(const uint32_t*)bp;
                    b[j][1] = *(const uint32_t*)(bp + 8);
                }
#pragma unroll
                for (int i = 0; i < 4; i++)
#pragma unroll
                    for (int j = 0; j < 4; j++) mma16816(acc[i][j], a[i], b[j]);
            }
        }
        __syncthreads();
    }

    // Epilogue: bias, split to hi/lo bf16, head-split store
#pragma unroll
    for (int i = 0; i < 4; i++) {
#pragma unroll
        for (int j = 0; j < 4; j++) {
            int col = n0 + wn * 32 + 8 * j + (lane & 3) * 2;
            float b0 = bias[col], b1 = bias[col + 1];
            int h = col >> 6, c = col & 63;
#pragma unroll
            for (int half = 0; half < 2; half++) {
                int row = m0 + wm * 64 + 16 * i + (lane >> 2) + 8 * half;
                int bidx = row >> 11;
                int s    = row & (SL - 1);
                float v0 = acc[i][j][2 * half + 0] + b0;
                float v1 = acc[i][j][2 * half + 1] + b1;
                uint32_t hh, ll;
                split2(v0, v1, hh, ll);
                size_t off = (((size_t)bidx * NH + h) * SL + s) * DK + c;
                *(uint32_t*)(dh + off) = hh;
                *(uint32_t*)(dl + off) = ll;
            }
        }
    }
}

// ---------------------------------------------------------------------------
// Flash attention via mma.sync bf16 split-precision.
// grid (16, 48), 256 thr (8 warps x 16 q-rows). Bc = 64.
// ---------------------------------------------------------------------------
#define SCALE 0.1803368801111137f    // (1/8) * log2(e)

__global__ __launch_bounds__(256) void attn_mma_kernel(float* __restrict__ out)
{
    extern __shared__ __nv_bfloat16 sm[];
    __nv_bfloat16* Qh  = sm;                    // [128][ST]
    __nv_bfloat16* Ql  = sm + 128 * ST;
    __nv_bfloat16* Kh  = sm + 2 * 128 * ST;     // [64][ST]
    __nv_bfloat16* Kl  = Kh + 64 * ST;
    __nv_bfloat16* Vth = Kl + 64 * ST;          // [64 d][ST] transposed
    __nv_bfloat16* Vtl = Vth + 64 * ST;

    const int tid  = threadIdx.x;
    const int lane = tid & 31, wid = tid >> 5;
    const int bh = blockIdx.y;
    const int q0 = blockIdx.x * 128;

    const __nv_bfloat16* qh = g_qh + (size_t)bh * SL * DK;
    const __nv_bfloat16* ql = g_ql + (size_t)bh * SL * DK;
    const __nv_bfloat16* kh = g_kh + (size_t)bh * SL * DK;
    const __nv_bfloat16* kl = g_kl + (size_t)bh * SL * DK;
    const __nv_bfloat16* vh = g_vh + (size_t)bh * SL * DK;
    const __nv_bfloat16* vl = g_vl + (size_t)bh * SL * DK;

    // Load Q tiles (hi/lo): 128x64 = 1024 float4 each, 4/thread
#pragma unroll
    for (int r = 0; r < 4; r++) {
        int idx = tid + r * 256;
        int row = idx >> 3;
        int c8  = (idx & 7) * 8;
        *(float4*)(Qh + row * ST + c8) =
            *(const float4*)(qh + (size_t)(q0 + row) * DK + c8);
        *(float4*)(Ql + row * ST + c8) =
            *(const float4*)(ql + (size_t)(q0 + row) * DK + c8);
    }

    float m0v = -1e30f, m1v = -1e30f, l0 = 0.f, l1 = 0.f;
    float ctx[8][4];
#pragma unroll
    for (int j = 0; j < 8; j++)
#pragma unroll
        for (int q = 0; q < 4; q++) ctx[j][q] = 0.f;

    for (int t = 0; t < SL / 64; t++) {
        const int n0 = t * 64;
        // K tiles (hi/lo): 64x64 = 512 float4 each, 2/thread
#pragma unroll
        for (int r = 0; r < 2; r++) {
            int idx = tid + r * 256;
            int row = idx >> 3;
            int c8  = (idx & 7) * 8;
            *(float4*)(Kh + row * ST + c8) =
                *(const float4*)(kh + (size_t)(n0 + row) * DK + c8);
            *(float4*)(Kl + row * ST + c8) =
                *(const float4*)(kl + (size_t)(n0 + row) * DK + c8);
        }
        // V tiles transposed: thread owns row s = tid>>2, d-range (tid&3)*16..+15
        {
            int s  = tid >> 2;
            int dg = (tid & 3) * 16;
#pragma unroll
            for (int half = 0; half < 2; half++) {
                int d0 = dg + half * 8;
                float4 a = *(const float4*)(vh + (size_t)(n0 + s) * DK + d0);
                float4 b = *(const float4*)(vl + (size_t)(n0 + s) * DK + d0);
                const __nv_bfloat16* pa = (const __nv_bfloat16*)&a;
                const __nv_bfloat16* pb = (const __nv_bfloat16*)&b;
#pragma unroll
                for (int i = 0; i < 8; i++) {
                    Vth[(d0 + i) * ST + s] = pa[i];
                    Vtl[(d0 + i) * ST + s] = pb[i];
                }
            }
        }
        __syncthreads();

        // S = Q K^T (split, 3 passes), accum fp32
        float s[8][4];
#pragma unroll
        for (int j = 0; j < 8; j++)
#pragma unroll
            for (int q = 0; q < 4; q++) s[j][q] = 0.f;

#pragma unroll
        for (int pass = 0; pass < 3; pass++) {
            const __nv_bfloat16* As = (pass == 1) ? Ql : Qh;
            const __nv_bfloat16* Bs = (pass == 2) ? Kl : Kh;
#pragma unroll
            for (int ks = 0; ks < 4; ks++) {
                const int kb = ks * 16 + (lane & 3) * 2;
                uint32_t a[4];
                const __nv_bfloat16* ap = As + (wid * 16 + (lane >> 2)) * ST + kb;
                a[0] = *(const uint32_t*)ap;
                a[1] = *(const uint32_t*)(ap + 8 * ST);
                a[2] = *(const uint32_t*)(ap + 8);
                a[3] = *(const uint32_t*)(ap + 8 * ST + 8);
#pragma unroll
                for (int j = 0; j < 8; j++) {
                    uint32_t b[2];
                    const __nv_bfloat16* bp = Bs + (8 * j + (lane >> 2)) * ST + kb;
                    b[0] = *(const uint32_t*)bp;
                    b[1] = *(const uint32_t*)(bp + 8);
                    mma16816(s[j], a, b);
                }
            }
        }

        // Online softmax in log2 domain (rows lane>>2 and +8)
        float mx0 = -1e30f, mx1 = -1e30f;
#pragma unroll
        for (int j = 0; j < 8; j++) {
            s[j][0] *= SCALE; s[j][1] *= SCALE;
            s[j][2] *= SCALE; s[j][3] *= SCALE;
            mx0 = fmaxf(mx0, fmaxf(s[j][0], s[j][1]));
            mx1 = fmaxf(mx1, fmaxf(s[j][2], s[j][3]));
        }
        mx0 = fmaxf(mx0, __shfl_xor_sync(0xffffffffu, mx0, 1));
        mx0 = fmaxf(mx0, __shfl_xor_sync(0xffffffffu, mx0, 2));
        mx1 = fmaxf(mx1, __shfl_xor_sync(0xffffffffu, mx1, 1));
        mx1 = fmaxf(mx1, __shfl_xor_sync(0xffffffffu, mx1, 2));

        float mn0 = fmaxf(m0v, mx0), mn1 = fmaxf(m1v, mx1);
        float al0 = exp2a(m0v - mn0), al1 = exp2a(m1v - mn1);
        float rs0 = 0.f, rs1 = 0.f;
#pragma unroll
        for (int j = 0; j < 8; j++) {
            s[j][0] = exp2a(s[j][0] - mn0);
            s[j][1] = exp2a(s[j][1] - mn0);
            s[j][2] = exp2a(s[j][2] - mn1);
            s[j][3] = exp2a(s[j][3] - mn1);
            rs0 += s[j][0] + s[j][1];
            rs1 += s[j][2] + s[j][3];
        }
        rs0 += __shfl_xor_sync(0xffffffffu, rs0, 1);
        rs0 += __shfl_xor_sync(0xffffffffu, rs0, 2);
        rs1 += __shfl_xor_sync(0xffffffffu, rs1, 1);
        rs1 += __shfl_xor_sync(0xffffffffu, rs1, 2);

        l0 = l0 * al0 + rs0;  m0v = mn0;
        l1 = l1 * al1 + rs1;  m1v = mn1;
#pragma unroll
        for (int j = 0; j < 8; j++) {
            ctx[j][0] *= al0; ctx[j][1] *= al0;
            ctx[j][2] *= al1; ctx[j][3] *= al1;
        }

        // P fragments (hi/lo) built in-register from S accumulators
        uint32_t ph[4][4], pl[4][4];
#pragma unroll
        for (int kk = 0; kk < 4; kk++) {
            split2(s[2 * kk][0],     s[2 * kk][1],     ph[kk][0], pl[kk][0]);
            split2(s[2 * kk][2],     s[2 * kk][3],     ph[kk][1], pl[kk][1]);
            split2(s[2 * kk + 1][0], s[2 * kk + 1][1], ph[kk][2], pl[kk][2]);
            split2(s[2 * kk + 1][2], s[2 * kk + 1][3], ph[kk][3], pl[kk][3]);
        }

        // ctx += P V (split, 3 passes)
#pragma unroll
        for (int pass = 0; pass < 3; pass++) {
            const uint32_t (*Ap)[4] = (pass == 1) ? pl : ph;
            const __nv_bfloat16* Bs = (pass == 2) ? Vtl : Vth;
#pragma unroll
            for (int kk = 0; kk < 4; kk++) {
                const int kb = kk * 16 + (lane & 3) * 2;
#pragma unroll
                for (int j = 0; j < 8; j++) {
                    uint32_t b[2];
                    const __nv_bfloat16* bp = Bs + (8 * j + (lane >> 2)) * ST + kb;
                    b[0] = *(const uint32_t*)bp;
                    b[1] = *(const uint32_t*)(bp + 8);
                    mma16816(ctx[j], Ap[kk], b);
                }
            }
        }
        __syncthreads();
    }

    // Epilogue
    const int b_idx = bh / NH;
    const int h     = bh % NH;
    const float inv0 = 1.0f / l0, inv1 = 1.0f / l1;
    const int r0 = q0 + wid * 16 + (lane >> 2);
#pragma unroll
    for (int j = 0; j < 8; j++) {
        int d = 8 * j + (lane & 3) * 2;
        float* o0 = out + ((size_t)b_idx * SL + r0) * DM + h * DK + d;
        float* o1 = o0 + 8 * DM;
        *(float2*)o0 = make_float2(ctx[j][0] * inv0, ctx[j][1] * inv0);
        *(float2*)o1 = make_float2(ctx[j][2] * inv1, ctx[j][3] * inv1);
    }
}

// ---------------------------------------------------------------------------
extern "C" void kernel_launch(void* const* d_in, const int* in_sizes, int n_in,
                              void* d_out, int out_size)
{
    const float* query = (const float*)d_in[0];
    const float* key_  = (const float*)d_in[1];
    const float* value = (const float*)d_in[2];
    const float* W_Q   = (const float*)d_in[3];
    const float* b_Q   = (const float*)d_in[4];
    const float* W_K   = (const float*)d_in[5];
    const float* b_K   = (const float*)d_in[6];
    const float* W_V   = (const float*)d_in[7];
    const float* b_V   = (const float*)d_in[8];
    float* out = (float*)d_out;

    {
        dim3 g((MROWS * DM / 4) / 256, 3);
        convert_x_kernel<<<g, 256>>>(query, key_, value);
    }
    {
        dim3 g(DM / 32, DM / 32, 3);
        convert_w_kernel<<<g, dim3(32, 8)>>>(W_Q, W_K, W_V);
    }
    {
        const int smem = 4 * 128 * ST * 2;   // 73728 B
        cudaFuncSetAttribute(qkv_proj_mma_kernel,
                             cudaFuncAttributeMaxDynamicSharedMemorySize, smem);
        dim3 g(MROWS / 128, DM / 128, 3);
        qkv_proj_mma_kernel<<<g, 256, smem>>>(b_Q, b_K, b_V);
    }
    {
        const int smem = (2 * 128 + 4 * 64) * ST * 2;   // 73728 B
        cudaFuncSetAttribute(attn_mma_kernel,
                             cudaFuncAttributeMaxDynamicSharedMemorySize, smem);
        dim3 g(SL / 128, BH);
        attn_mma_kernel<<<g, 256, smem>>>(out);
    }
}

// round 6
// speedup vs baseline: 2.6475x; 1.1385x over previous
#include <cuda_runtime.h>
#include <cuda_bf16.h>
#include <math.h>
#include <stdint.h>

#define NB 4
#define NH 12
#define SL 2048
#define DK 64
#define DM 768
#define BH (NB*NH)
#define MROWS (NB*SL)          // 8192
#define ST 72                  // smem row stride in bf16 elems (144B)

// ---------------------------------------------------------------------------
// Device scratch (static; no allocation)
// ---------------------------------------------------------------------------
__device__ __nv_bfloat16 g_xh[3][(size_t)MROWS * DM];
__device__ __nv_bfloat16 g_xl[3][(size_t)MROWS * DM];
__device__ __nv_bfloat16 g_wth[3][DM * DM];   // W^T (n,k), hi
__device__ __nv_bfloat16 g_wtl[3][DM * DM];   // W^T (n,k), lo

__device__ __nv_bfloat16 g_qh[(size_t)BH * SL * DK];
__device__ __nv_bfloat16 g_ql[(size_t)BH * SL * DK];
__device__ __nv_bfloat16 g_kh[(size_t)BH * SL * DK];
__device__ __nv_bfloat16 g_kl[(size_t)BH * SL * DK];
__device__ __nv_bfloat16 g_vh[(size_t)BH * SL * DK];
__device__ __nv_bfloat16 g_vl[(size_t)BH * SL * DK];

// ---------------------------------------------------------------------------
// Helpers
// ---------------------------------------------------------------------------
__device__ __forceinline__ void mma16816(float* c, const uint32_t* a,
                                         const uint32_t* b) {
    asm volatile(
        "mma.sync.aligned.m16n8k16.row.col.f32.bf16.bf16.f32 "
        "{%0,%1,%2,%3}, {%4,%5,%6,%7}, {%8,%9}, {%0,%1,%2,%3};\n"
        : "+f"(c[0]), "+f"(c[1]), "+f"(c[2]), "+f"(c[3])
        : "r"(a[0]), "r"(a[1]), "r"(a[2]), "r"(a[3]), "r"(b[0]), "r"(b[1]));
}

// FFMA-pipe exp2 (no MUFU): degree-6 poly on [0,1) + exponent-bit scaling.
__device__ __forceinline__ float exp2a(float x) {
    x = fmaxf(x, -80.f);
    float xi = floorf(x);
    float f = x - xi;
    float p = 1.53533e-4f;
    p = fmaf(p, f, 1.33989e-3f);
    p = fmaf(p, f, 9.61844e-3f);
    p = fmaf(p, f, 5.55033e-2f);
    p = fmaf(p, f, 2.40226e-1f);
    p = fmaf(p, f, 6.93147e-1f);
    p = fmaf(p, f, 1.0f);
    return p * __int_as_float(((int)xi + 127) << 23);
}

__device__ __forceinline__ void split2(float a, float b, uint32_t& h, uint32_t& l) {
    __nv_bfloat162 H = __floats2bfloat162_rn(a, b);
    float ra = a - __bfloat162float(H.x);
    float rb = b - __bfloat162float(H.y);
    __nv_bfloat162 L = __floats2bfloat162_rn(ra, rb);
    h = *(uint32_t*)&H;
    l = *(uint32_t*)&L;
}

// ---------------------------------------------------------------------------
// Conversion: X -> (hi, lo) bf16 split.
// ---------------------------------------------------------------------------
__global__ __launch_bounds__(256) void convert_x_kernel(
    const float* __restrict__ q, const float* __restrict__ k,
    const float* __restrict__ v)
{
    const int sel = blockIdx.y;
    const float* src = (sel == 0) ? q : (sel == 1) ? k : v;
    __nv_bfloat16* xh = g_xh[sel];
    __nv_bfloat16* xl = g_xl[sel];

    size_t idx = (size_t)blockIdx.x * blockDim.x + threadIdx.x;  // float4 index
    float4 x = ((const float4*)src)[idx];
    float vv[4] = {x.x, x.y, x.z, x.w};
    uint32_t h[2], l[2];
    split2(vv[0], vv[1], h[0], l[0]);
    split2(vv[2], vv[3], h[1], l[1]);
    ((uint32_t*)xh)[idx * 2 + 0] = h[0];
    ((uint32_t*)xh)[idx * 2 + 1] = h[1];
    ((uint32_t*)xl)[idx * 2 + 0] = l[0];
    ((uint32_t*)xl)[idx * 2 + 1] = l[1];
}

// ---------------------------------------------------------------------------
// Conversion: W[k][n] -> W^T[n][k] (hi, lo) bf16.
// ---------------------------------------------------------------------------
__global__ void convert_w_kernel(const float* __restrict__ Wq,
                                 const float* __restrict__ Wk,
                                 const float* __restrict__ Wv)
{
    __shared__ float t[32][33];
    const int sel = blockIdx.z;
    const float* W = (sel == 0) ? Wq : (sel == 1) ? Wk : Wv;
    const int k0 = blockIdx.x * 32;
    const int n0 = blockIdx.y * 32;
    const int tx = threadIdx.x, ty = threadIdx.y;

#pragma unroll
    for (int r = 0; r < 4; r++)
        t[ty + 8 * r][tx] = W[(size_t)(k0 + ty + 8 * r) * DM + n0 + tx];
    __syncthreads();

#pragma unroll
    for (int r = 0; r < 4; r++) {
        float v = t[tx][ty + 8 * r];
        __nv_bfloat16 h = __float2bfloat16_rn(v);
        __nv_bfloat16 l = __float2bfloat16_rn(v - __bfloat162float(h));
        size_t o = (size_t)(n0 + ty + 8 * r) * DM + k0 + tx;
        g_wth[sel][o] = h;
        g_wtl[sel][o] = l;
    }
}

// ---------------------------------------------------------------------------
// QKV projection via mma.sync bf16 split-precision.
// grid (64, 6, 3), 256 thr (8 warps: 2x4, warp tile 64x32).
// Outputs head-split bf16 hi/lo.
// ---------------------------------------------------------------------------
__global__ __launch_bounds__(256) void qkv_proj_mma_kernel(
    const float* __restrict__ bq, const float* __restrict__ bk,
    const float* __restrict__ bv)
{
    extern __shared__ __nv_bfloat16 sm[];
    __nv_bfloat16* Xh = sm;                 // [128][ST]
    __nv_bfloat16* Xl = sm + 128 * ST;
    __nv_bfloat16* Wh = sm + 2 * 128 * ST;
    __nv_bfloat16* Wl = sm + 3 * 128 * ST;

    const int tid  = threadIdx.x;
    const int lane = tid & 31, wid = tid >> 5;
    const int wm = wid >> 2, wn = wid & 3;       // warp at (wm*64, wn*32)
    const int m0 = blockIdx.x * 128;
    const int n0 = blockIdx.y * 128;
    const int sel = blockIdx.z;

    const __nv_bfloat16* Agh = g_xh[sel];
    const __nv_bfloat16* Agl = g_xl[sel];
    const __nv_bfloat16* Bgh = g_wth[sel];
    const __nv_bfloat16* Bgl = g_wtl[sel];
    const float* bias = (sel == 0) ? bq : (sel == 1) ? bk : bv;
    __nv_bfloat16* dh = (sel == 0) ? g_qh : (sel == 1) ? g_kh : g_vh;
    __nv_bfloat16* dl = (sel == 0) ? g_ql : (sel == 1) ? g_kl : g_vl;

    float acc[4][4][4];
#pragma unroll
    for (int i = 0; i < 4; i++)
#pragma unroll
        for (int j = 0; j < 4; j++)
#pragma unroll
            for (int q = 0; q < 4; q++) acc[i][j][q] = 0.f;

    for (int ch = 0; ch < DM / 64; ch++) {
        const int k0 = ch * 64;
#pragma unroll
        for (int r = 0; r < 4; r++) {
            int idx = tid + r * 256;
            int row = idx >> 3;
            int c8  = (idx & 7) * 8;
            *(float4*)(Xh + row * ST + c8) =
                *(const float4*)(Agh + (size_t)(m0 + row) * DM + k0 + c8);
            *(float4*)(Xl + row * ST + c8) =
                *(const float4*)(Agl + (size_t)(m0 + row) * DM + k0 + c8);
            *(float4*)(Wh + row * ST + c8) =
                *(const float4*)(Bgh + (size_t)(n0 + row) * DM + k0 + c8);
            *(float4*)(Wl + row * ST + c8) =
                *(const float4*)(Bgl + (size_t)(n0 + row) * DM + k0 + c8);
        }
        __syncthreads();

#pragma unroll
        for (int ks = 0; ks < 4; ks++) {
            const int kb = ks * 16 + (lane & 3) * 2;
            uint32_t ah[4][4], al[4][4];
#pragma unroll
            for (int i = 0; i < 4; i++) {
                const __nv_bfloat16* ap =
                    Xh + (wm * 64 + 16 * i + (lane >> 2)) * ST + kb;
                const __nv_bfloat16* aq =
                    Xl + (wm * 64 + 16 * i + (lane >> 2)) * ST + kb;
                ah[i][0] = *(const uint32_t*)ap;
                ah[i][1] = *(const uint32_t*)(ap + 8 * ST);
                ah[i][2] = *(const uint32_t*)(ap + 8);
                ah[i][3] = *(const uint32_t*)(ap + 8 * ST + 8);
                al[i][0] = *(const uint32_t*)aq;
                al[i][1] = *(const uint32_t*)(aq + 8 * ST);
                al[i][2] = *(const uint32_t*)(aq + 8);
                al[i][3] = *(const uint32_t*)(aq + 8 * ST + 8);
            }
#pragma unroll
            for (int j = 0; j < 4; j++) {
                const __nv_bfloat16* bp =
                    Wh + (wn * 32 + 8 * j + (lane >> 2)) * ST + kb;
                const __nv_bfloat16* bq2 =
                    Wl + (wn * 32 + 8 * j + (lane >> 2)) * ST + kb;
                uint32_t bh[2], bl[2];
                bh[0] = *(const uint32_t*)bp;
                bh[1] = *(const uint32_t*)(bp + 8);
                bl[0] = *(const uint32_t*)bq2;
                bl[1] = *(const uint32_t*)(bq2 + 8);
#pragma unroll
                for (int i = 0; i < 4; i++) {
                    mma16816(acc[i][j], ah[i], bh);
                    mma16816(acc[i][j], al[i], bh);
                    mma16816(acc[i][j], ah[i], bl);
                }
            }
        }
        __syncthreads();
    }

    // Epilogue: bias, split to hi/lo bf16, head-split store
#pragma unroll
    for (int i = 0; i < 4; i++) {
#pragma unroll
        for (int j = 0; j < 4; j++) {
            int col = n0 + wn * 32 + 8 * j + (lane & 3) * 2;
            float b0 = bias[col], b1 = bias[col + 1];
            int h = col >> 6, c = col & 63;
#pragma unroll
            for (int half = 0; half < 2; half++) {
                int row = m0 + wm * 64 + 16 * i + (lane >> 2) + 8 * half;
                int bidx = row >> 11;
                int s    = row & (SL - 1);
                float v0 = acc[i][j][2 * half + 0] + b0;
                float v1 = acc[i][j][2 * half + 1] + b1;
                uint32_t hh, ll;
                split2(v0, v1, hh, ll);
                size_t off = (((size_t)bidx * NH + h) * SL + s) * DK + c;
                *(uint32_t*)(dh + off) = hh;
                *(uint32_t*)(dl + off) = ll;
            }
        }
    }
}

// ---------------------------------------------------------------------------
// Flash attention via mma.sync bf16 split-precision.
// grid (SL/64 = 32, 48), 128 thr (4 warps x 16 q-rows). Br = 64, Bc = 64.
// 3 CTAs/SM target: independent sync domains hide the softmax phase.
// ---------------------------------------------------------------------------
#define SCALE 0.1803368801111137f    // (1/8) * log2(e)

__global__ __launch_bounds__(128, 3) void attn_mma_kernel(float* __restrict__ out)
{
    extern __shared__ __nv_bfloat16 sm[];
    __nv_bfloat16* Qh  = sm;                    // [64][ST]
    __nv_bfloat16* Ql  = sm + 64 * ST;
    __nv_bfloat16* Kh  = sm + 2 * 64 * ST;
    __nv_bfloat16* Kl  = sm + 3 * 64 * ST;
    __nv_bfloat16* Vth = sm + 4 * 64 * ST;      // [64 d][ST] transposed
    __nv_bfloat16* Vtl = sm + 5 * 64 * ST;

    const int tid  = threadIdx.x;
    const int lane = tid & 31, wid = tid >> 5;
    const int bh = blockIdx.y;
    const int q0 = blockIdx.x * 64;

    const __nv_bfloat16* qh = g_qh + (size_t)bh * SL * DK;
    const __nv_bfloat16* ql = g_ql + (size_t)bh * SL * DK;
    const __nv_bfloat16* kh = g_kh + (size_t)bh * SL * DK;
    const __nv_bfloat16* kl = g_kl + (size_t)bh * SL * DK;
    const __nv_bfloat16* vh = g_vh + (size_t)bh * SL * DK;
    const __nv_bfloat16* vl = g_vl + (size_t)bh * SL * DK;

    // Load Q tiles (hi/lo): 64x64 = 512 float4 each, 4/thread
#pragma unroll
    for (int r = 0; r < 4; r++) {
        int idx = tid + r * 128;
        int row = idx >> 3;
        int c8  = (idx & 7) * 8;
        *(float4*)(Qh + row * ST + c8) =
            *(const float4*)(qh + (size_t)(q0 + row) * DK + c8);
        *(float4*)(Ql + row * ST + c8) =
            *(const float4*)(ql + (size_t)(q0 + row) * DK + c8);
    }

    float m0v = -1e30f, m1v = -1e30f, l0 = 0.f, l1 = 0.f;
    float ctx[8][4];
#pragma unroll
    for (int j = 0; j < 8; j++)
#pragma unroll
        for (int q = 0; q < 4; q++) ctx[j][q] = 0.f;

    for (int t = 0; t < SL / 64; t++) {
        const int n0 = t * 64;
        // K tiles (hi/lo): 64x64 = 512 float4 each, 4/thread
#pragma unroll
        for (int r = 0; r < 4; r++) {
            int idx = tid + r * 128;
            int row = idx >> 3;
            int c8  = (idx & 7) * 8;
            *(float4*)(Kh + row * ST + c8) =
                *(const float4*)(kh + (size_t)(n0 + row) * DK + c8);
            *(float4*)(Kl + row * ST + c8) =
                *(const float4*)(kl + (size_t)(n0 + row) * DK + c8);
        }
        // V transposed: thread owns row s = tid>>1, d-range (tid&1)*32..+31
        {
            int s  = tid >> 1;
            int dg = (tid & 1) * 32;
#pragma unroll
            for (int half = 0; half < 4; half++) {
                int d0 = dg + half * 8;
                float4 a = *(const float4*)(vh + (size_t)(n0 + s) * DK + d0);
                float4 b = *(const float4*)(vl + (size_t)(n0 + s) * DK + d0);
                const __nv_bfloat16* pa = (const __nv_bfloat16*)&a;
                const __nv_bfloat16* pb = (const __nv_bfloat16*)&b;
#pragma unroll
                for (int i = 0; i < 8; i++) {
                    Vth[(d0 + i) * ST + s] = pa[i];
                    Vtl[(d0 + i) * ST + s] = pb[i];
                }
            }
        }
        __syncthreads();

        // S = Q K^T (split, 3 mma per b-frag), accum fp32
        float s[8][4];
#pragma unroll
        for (int j = 0; j < 8; j++)
#pragma unroll
            for (int q = 0; q < 4; q++) s[j][q] = 0.f;

#pragma unroll
        for (int ks = 0; ks < 4; ks++) {
            const int kb = ks * 16 + (lane & 3) * 2;
            uint32_t ah[4], al[4];
            {
                const __nv_bfloat16* ap = Qh + (wid * 16 + (lane >> 2)) * ST + kb;
                const __nv_bfloat16* aq = Ql + (wid * 16 + (lane >> 2)) * ST + kb;
                ah[0] = *(const uint32_t*)ap;
                ah[1] = *(const uint32_t*)(ap + 8 * ST);
                ah[2] = *(const uint32_t*)(ap + 8);
                ah[3] = *(const uint32_t*)(ap + 8 * ST + 8);
                al[0] = *(const uint32_t*)aq;
                al[1] = *(const uint32_t*)(aq + 8 * ST);
                al[2] = *(const uint32_t*)(aq + 8);
                al[3] = *(const uint32_t*)(aq + 8 * ST + 8);
            }
#pragma unroll
            for (int j = 0; j < 8; j++) {
                const __nv_bfloat16* bp = Kh + (8 * j + (lane >> 2)) * ST + kb;
                const __nv_bfloat16* bq2 = Kl + (8 * j + (lane >> 2)) * ST + kb;
                uint32_t bhr[2], blr[2];
                bhr[0] = *(const uint32_t*)bp;
                bhr[1] = *(const uint32_t*)(bp + 8);
                blr[0] = *(const uint32_t*)bq2;
                blr[1] = *(const uint32_t*)(bq2 + 8);
                mma16816(s[j], ah, bhr);
                mma16816(s[j], al, bhr);
                mma16816(s[j], ah, blr);
            }
        }

        // Online softmax in log2 domain (rows lane>>2 and +8)
        float mx0 = -1e30f, mx1 = -1e30f;
#pragma unroll
        for (int j = 0; j < 8; j++) {
            s[j][0] *= SCALE; s[j][1] *= SCALE;
            s[j][2] *= SCALE; s[j][3] *= SCALE;
            mx0 = fmaxf(mx0, fmaxf(s[j][0], s[j][1]));
            mx1 = fmaxf(mx1, fmaxf(s[j][2], s[j][3]));
        }
        mx0 = fmaxf(mx0, __shfl_xor_sync(0xffffffffu, mx0, 1));
        mx0 = fmaxf(mx0, __shfl_xor_sync(0xffffffffu, mx0, 2));
        mx1 = fmaxf(mx1, __shfl_xor_sync(0xffffffffu, mx1, 1));
        mx1 = fmaxf(mx1, __shfl_xor_sync(0xffffffffu, mx1, 2));

        float mn0 = fmaxf(m0v, mx0), mn1 = fmaxf(m1v, mx1);
        float al0 = exp2a(m0v - mn0), al1 = exp2a(m1v - mn1);
        float rs0 = 0.f, rs1 = 0.f;
#pragma unroll
        for (int j = 0; j < 8; j++) {
            s[j][0] = exp2a(s[j][0] - mn0);
            s[j][1] = exp2a(s[j][1] - mn0);
            s[j][2] = exp2a(s[j][2] - mn1);
            s[j][3] = exp2a(s[j][3] - mn1);
            rs0 += s[j][0] + s[j][1];
            rs1 += s[j][2] + s[j][3];
        }
        rs0 += __shfl_xor_sync(0xffffffffu, rs0, 1);
        rs0 += __shfl_xor_sync(0xffffffffu, rs0, 2);
        rs1 += __shfl_xor_sync(0xffffffffu, rs1, 1);
        rs1 += __shfl_xor_sync(0xffffffffu, rs1, 2);

        l0 = l0 * al0 + rs0;  m0v = mn0;
        l1 = l1 * al1 + rs1;  m1v = mn1;
#pragma unroll
        for (int j = 0; j < 8; j++) {
            ctx[j][0] *= al0; ctx[j][1] *= al0;
            ctx[j][2] *= al1; ctx[j][3] *= al1;
        }

        // ctx += P V (split P built per-kk in registers; 3 mma per b-frag)
#pragma unroll
        for (int kk = 0; kk < 4; kk++) {
            const int kb = kk * 16 + (lane & 3) * 2;
            uint32_t ph[4], pl[4];
            split2(s[2 * kk][0],     s[2 * kk][1],     ph[0], pl[0]);
            split2(s[2 * kk][2],     s[2 * kk][3],     ph[1], pl[1]);
            split2(s[2 * kk + 1][0], s[2 * kk + 1][1], ph[2], pl[2]);
            split2(s[2 * kk + 1][2], s[2 * kk + 1][3], ph[3], pl[3]);
#pragma unroll
            for (int j = 0; j < 8; j++) {
                const __nv_bfloat16* bp = Vth + (8 * j + (lane >> 2)) * ST + kb;
                const __nv_bfloat16* bq2 = Vtl + (8 * j + (lane >> 2)) * ST + kb;
                uint32_t bhr[2], blr[2];
                bhr[0] = *(const uint32_t*)bp;
                bhr[1] = *(const uint32_t*)(bp + 8);
                blr[0] = *(const uint32_t*)bq2;
                blr[1] = *(const uint32_t*)(bq2 + 8);
                mma16816(ctx[j], ph, bhr);
                mma16816(ctx[j], pl, bhr);
                mma16816(ctx[j], ph, blr);
            }
        }
        __syncthreads();
    }

    // Epilogue
    const int b_idx = bh / NH;
    const int h     = bh % NH;
    const float inv0 = 1.0f / l0, inv1 = 1.0f / l1;
    const int r0 = q0 + wid * 16 + (lane >> 2);
#pragma unroll
    for (int j = 0; j < 8; j++) {
        int d = 8 * j + (lane & 3) * 2;
        float* o0 = out + ((size_t)b_idx * SL + r0) * DM + h * DK + d;
        float* o1 = o0 + 8 * DM;
        *(float2*)o0 = make_float2(ctx[j][0] * inv0, ctx[j][1] * inv0);
        *(float2*)o1 = make_float2(ctx[j][2] * inv1, ctx[j][3] * inv1);
    }
}

// ---------------------------------------------------------------------------
extern "C" void kernel_launch(void* const* d_in, const int* in_sizes, int n_in,
                              void* d_out, int out_size)
{
    const float* query = (const float*)d_in[0];
    const float* key_  = (const float*)d_in[1];
    const float* value = (const float*)d_in[2];
    const float* W_Q   = (const float*)d_in[3];
    const float* b_Q   = (const float*)d_in[4];
    const float* W_K   = (const float*)d_in[5];
    const float* b_K   = (const float*)d_in[6];
    const float* W_V   = (const float*)d_in[7];
    const float* b_V   = (const float*)d_in[8];
    float* out = (float*)d_out;

    {
        dim3 g((MROWS * DM / 4) / 256, 3);
        convert_x_kernel<<<g, 256>>>(query, key_, value);
    }
    {
        dim3 g(DM / 32, DM / 32, 3);
        convert_w_kernel<<<g, dim3(32, 8)>>>(W_Q, W_K, W_V);
    }
    {
        const int smem = 4 * 128 * ST * 2;   // 73728 B
        cudaFuncSetAttribute(qkv_proj_mma_kernel,
                             cudaFuncAttributeMaxDynamicSharedMemorySize, smem);
        dim3 g(MROWS / 128, DM / 128, 3);
        qkv_proj_mma_kernel<<<g, 256, smem>>>(b_Q, b_K, b_V);
    }
    {
        const int smem = 6 * 64 * ST * 2;    // 55296 B
        cudaFuncSetAttribute(attn_mma_kernel,
                             cudaFuncAttributeMaxDynamicSharedMemorySize, smem);
        dim3 g(SL / 64, BH);
        attn_mma_kernel<<<g, 128, smem>>>(out);
    }
}

// round 7
// speedup vs baseline: 3.3097x; 1.2501x over previous
#include <cuda_runtime.h>
#include <cuda_bf16.h>
#include <math.h>
#include <stdint.h>

#define NB 4
#define NH 12
#define SL 2048
#define DK 64
#define DM 768
#define BH (NB*NH)
#define MROWS (NB*SL)          // 8192
#define ST 72                  // smem row stride in bf16 elems (144B)

// ---------------------------------------------------------------------------
// Device scratch (static; no allocation)
// ---------------------------------------------------------------------------
__device__ __nv_bfloat16 g_xh[3][(size_t)MROWS * DM];
__device__ __nv_bfloat16 g_xl[3][(size_t)MROWS * DM];
__device__ __nv_bfloat16 g_wth[3][DM * DM];   // W^T (n,k), hi
__device__ __nv_bfloat16 g_wtl[3][DM * DM];   // W^T (n,k), lo

__device__ __nv_bfloat16 g_qh[(size_t)BH * SL * DK];
__device__ __nv_bfloat16 g_ql[(size_t)BH * SL * DK];
__device__ __nv_bfloat16 g_kh[(size_t)BH * SL * DK];
__device__ __nv_bfloat16 g_kl[(size_t)BH * SL * DK];
__device__ __nv_bfloat16 g_vh[(size_t)BH * SL * DK];
__device__ __nv_bfloat16 g_vl[(size_t)BH * SL * DK];

// ---------------------------------------------------------------------------
// Helpers
// ---------------------------------------------------------------------------
__device__ __forceinline__ void mma16816(float* c, const uint32_t* a,
                                         const uint32_t* b) {
    asm volatile(
        "mma.sync.aligned.m16n8k16.row.col.f32.bf16.bf16.f32 "
        "{%0,%1,%2,%3}, {%4,%5,%6,%7}, {%8,%9}, {%0,%1,%2,%3};\n"
        : "+f"(c[0]), "+f"(c[1]), "+f"(c[2]), "+f"(c[3])
        : "r"(a[0]), "r"(a[1]), "r"(a[2]), "r"(a[3]), "r"(b[0]), "r"(b[1]));
}

__device__ __forceinline__ void ldsm_x4(uint32_t* r, uint32_t addr) {
    asm volatile(
        "ldmatrix.sync.aligned.m8n8.x4.shared.b16 {%0,%1,%2,%3}, [%4];"
        : "=r"(r[0]), "=r"(r[1]), "=r"(r[2]), "=r"(r[3]) : "r"(addr));
}

__device__ __forceinline__ void ldsm_x4_t(uint32_t* r, uint32_t addr) {
    asm volatile(
        "ldmatrix.sync.aligned.m8n8.x4.trans.shared.b16 {%0,%1,%2,%3}, [%4];"
        : "=r"(r[0]), "=r"(r[1]), "=r"(r[2]), "=r"(r[3]) : "r"(addr));
}

// FFMA-pipe exp2 (no MUFU): degree-6 poly on [0,1) + exponent-bit scaling.
__device__ __forceinline__ float exp2a(float x) {
    x = fmaxf(x, -80.f);
    float xi = floorf(x);
    float f = x - xi;
    float p = 1.53533e-4f;
    p = fmaf(p, f, 1.33989e-3f);
    p = fmaf(p, f, 9.61844e-3f);
    p = fmaf(p, f, 5.55033e-2f);
    p = fmaf(p, f, 2.40226e-1f);
    p = fmaf(p, f, 6.93147e-1f);
    p = fmaf(p, f, 1.0f);
    return p * __int_as_float(((int)xi + 127) << 23);
}

__device__ __forceinline__ void split2(float a, float b, uint32_t& h, uint32_t& l) {
    __nv_bfloat162 H = __floats2bfloat162_rn(a, b);
    float ra = a - __bfloat162float(H.x);
    float rb = b - __bfloat162float(H.y);
    __nv_bfloat162 L = __floats2bfloat162_rn(ra, rb);
    h = *(uint32_t*)&H;
    l = *(uint32_t*)&L;
}

// ---------------------------------------------------------------------------
// Conversion: X -> (hi, lo) bf16 split.
// ---------------------------------------------------------------------------
__global__ __launch_bounds__(256) void convert_x_kernel(
    const float* __restrict__ q, const float* __restrict__ k,
    const float* __restrict__ v)
{
    const int sel = blockIdx.y;
    const float* src = (sel == 0) ? q : (sel == 1) ? k : v;
    __nv_bfloat16* xh = g_xh[sel];
    __nv_bfloat16* xl = g_xl[sel];

    size_t idx = (size_t)blockIdx.x * blockDim.x + threadIdx.x;  // float4 index
    float4 x = ((const float4*)src)[idx];
    float vv[4] = {x.x, x.y, x.z, x.w};
    uint32_t h[2], l[2];
    split2(vv[0], vv[1], h[0], l[0]);
    split2(vv[2], vv[3], h[1], l[1]);
    ((uint32_t*)xh)[idx * 2 + 0] = h[0];
    ((uint32_t*)xh)[idx * 2 + 1] = h[1];
    ((uint32_t*)xl)[idx * 2 + 0] = l[0];
    ((uint32_t*)xl)[idx * 2 + 1] = l[1];
}

// ---------------------------------------------------------------------------
// Conversion: W[k][n] -> W^T[n][k] (hi, lo) bf16.
// ---------------------------------------------------------------------------
__global__ void convert_w_kernel(const float* __restrict__ Wq,
                                 const float* __restrict__ Wk,
                                 const float* __restrict__ Wv)
{
    __shared__ float t[32][33];
    const int sel = blockIdx.z;
    const float* W = (sel == 0) ? Wq : (sel == 1) ? Wk : Wv;
    const int k0 = blockIdx.x * 32;
    const int n0 = blockIdx.y * 32;
    const int tx = threadIdx.x, ty = threadIdx.y;

#pragma unroll
    for (int r = 0; r < 4; r++)
        t[ty + 8 * r][tx] = W[(size_t)(k0 + ty + 8 * r) * DM + n0 + tx];
    __syncthreads();

#pragma unroll
    for (int r = 0; r < 4; r++) {
        float v = t[tx][ty + 8 * r];
        __nv_bfloat16 h = __float2bfloat16_rn(v);
        __nv_bfloat16 l = __float2bfloat16_rn(v - __bfloat162float(h));
        size_t o = (size_t)(n0 + ty + 8 * r) * DM + k0 + tx;
        g_wth[sel][o] = h;
        g_wtl[sel][o] = l;
    }
}

// ---------------------------------------------------------------------------
// QKV projection via mma.sync bf16 split-precision (unchanged).
// grid (64, 6, 3), 256 thr (8 warps: 2x4, warp tile 64x32).
// ---------------------------------------------------------------------------
__global__ __launch_bounds__(256) void qkv_proj_mma_kernel(
    const float* __restrict__ bq, const float* __restrict__ bk,
    const float* __restrict__ bv)
{
    extern __shared__ __nv_bfloat16 sm[];
    __nv_bfloat16* Xh = sm;                 // [128][ST]
    __nv_bfloat16* Xl = sm + 128 * ST;
    __nv_bfloat16* Wh = sm + 2 * 128 * ST;
    __nv_bfloat16* Wl = sm + 3 * 128 * ST;

    const int tid  = threadIdx.x;
    const int lane = tid & 31, wid = tid >> 5;
    const int wm = wid >> 2, wn = wid & 3;
    const int m0 = blockIdx.x * 128;
    const int n0 = blockIdx.y * 128;
    const int sel = blockIdx.z;

    const __nv_bfloat16* Agh = g_xh[sel];
    const __nv_bfloat16* Agl = g_xl[sel];
    const __nv_bfloat16* Bgh = g_wth[sel];
    const __nv_bfloat16* Bgl = g_wtl[sel];
    const float* bias = (sel == 0) ? bq : (sel == 1) ? bk : bv;
    __nv_bfloat16* dh = (sel == 0) ? g_qh : (sel == 1) ? g_kh : g_vh;
    __nv_bfloat16* dl = (sel == 0) ? g_ql : (sel == 1) ? g_kl : g_vl;

    // ldmatrix lane offsets (bf16 elem units)
    const uint32_t a_loff = (uint32_t)((lane & 15) * ST + (lane >> 4) * 8);
    const uint32_t b_loff = (uint32_t)(((lane >> 4) * 8 + (lane & 7)) * ST +
                                       ((lane >> 3) & 1) * 8);

    float acc[4][4][4];
#pragma unroll
    for (int i = 0; i < 4; i++)
#pragma unroll
        for (int j = 0; j < 4; j++)
#pragma unroll
            for (int q = 0; q < 4; q++) acc[i][j][q] = 0.f;

    const uint32_t sXh = (uint32_t)__cvta_generic_to_shared(Xh);
    const uint32_t sXl = (uint32_t)__cvta_generic_to_shared(Xl);
    const uint32_t sWh = (uint32_t)__cvta_generic_to_shared(Wh);
    const uint32_t sWl = (uint32_t)__cvta_generic_to_shared(Wl);

    for (int ch = 0; ch < DM / 64; ch++) {
        const int k0 = ch * 64;
#pragma unroll
        for (int r = 0; r < 4; r++) {
            int idx = tid + r * 256;
            int row = idx >> 3;
            int c8  = (idx & 7) * 8;
            *(float4*)(Xh + row * ST + c8) =
                *(const float4*)(Agh + (size_t)(m0 + row) * DM + k0 + c8);
            *(float4*)(Xl + row * ST + c8) =
                *(const float4*)(Agl + (size_t)(m0 + row) * DM + k0 + c8);
            *(float4*)(Wh + row * ST + c8) =
                *(const float4*)(Bgh + (size_t)(n0 + row) * DM + k0 + c8);
            *(float4*)(Wl + row * ST + c8) =
                *(const float4*)(Bgl + (size_t)(n0 + row) * DM + k0 + c8);
        }
        __syncthreads();

#pragma unroll
        for (int ks = 0; ks < 4; ks++) {
            const uint32_t kb = ks * 16;
            uint32_t ah[4][4], al[4][4];
#pragma unroll
            for (int i = 0; i < 4; i++) {
                uint32_t off = (uint32_t)((wm * 64 + 16 * i) * ST) + kb + a_loff;
                ldsm_x4(ah[i], sXh + off * 2);
                ldsm_x4(al[i], sXl + off * 2);
            }
#pragma unroll
            for (int jp = 0; jp < 2; jp++) {
                uint32_t off = (uint32_t)((wn * 32 + 16 * jp) * ST) + kb + b_loff;
                uint32_t bh[4], bl[4];
                ldsm_x4(bh, sWh + off * 2);
                ldsm_x4(bl, sWl + off * 2);
#pragma unroll
                for (int i = 0; i < 4; i++) {
                    mma16816(acc[i][2 * jp],     ah[i], bh);
                    mma16816(acc[i][2 * jp],     al[i], bh);
                    mma16816(acc[i][2 * jp],     ah[i], bl);
                    mma16816(acc[i][2 * jp + 1], ah[i], bh + 2);
                    mma16816(acc[i][2 * jp + 1], al[i], bh + 2);
                    mma16816(acc[i][2 * jp + 1], ah[i], bl + 2);
                }
            }
        }
        __syncthreads();
    }

    // Epilogue: bias, split to hi/lo bf16, head-split store
#pragma unroll
    for (int i = 0; i < 4; i++) {
#pragma unroll
        for (int j = 0; j < 4; j++) {
            int col = n0 + wn * 32 + 8 * j + (lane & 3) * 2;
            float b0 = bias[col], b1 = bias[col + 1];
            int h = col >> 6, c = col & 63;
#pragma unroll
            for (int half = 0; half < 2; half++) {
                int row = m0 + wm * 64 + 16 * i + (lane >> 2) + 8 * half;
                int bidx = row >> 11;
                int s    = row & (SL - 1);
                float v0 = acc[i][j][2 * half + 0] + b0;
                float v1 = acc[i][j][2 * half + 1] + b1;
                uint32_t hh, ll;
                split2(v0, v1, hh, ll);
                size_t off = (((size_t)bidx * NH + h) * SL + s) * DK + c;
                *(uint32_t*)(dh + off) = hh;
                *(uint32_t*)(dl + off) = ll;
            }
        }
    }
}

// ---------------------------------------------------------------------------
// Flash attention via mma.sync + ldmatrix, split-precision bf16.
// grid (32, 48), 128 thr (4 warps x 16 q-rows). Br = 64, Bc = 64.
// V stored row-major; PV B-frags via ldmatrix.trans (no transpose stores).
// ---------------------------------------------------------------------------
#define SCALE 0.1803368801111137f    // (1/8) * log2(e)

__global__ __launch_bounds__(128, 3) void attn_mma_kernel(float* __restrict__ out)
{
    extern __shared__ __nv_bfloat16 sm[];
    __nv_bfloat16* Qh = sm;                    // [64][ST]
    __nv_bfloat16* Ql = sm + 64 * ST;
    __nv_bfloat16* Kh = sm + 2 * 64 * ST;
    __nv_bfloat16* Kl = sm + 3 * 64 * ST;
    __nv_bfloat16* Vh = sm + 4 * 64 * ST;      // row-major [s][d]
    __nv_bfloat16* Vl = sm + 5 * 64 * ST;

    const int tid  = threadIdx.x;
    const int lane = tid & 31, wid = tid >> 5;
    const int bh = blockIdx.y;
    const int q0 = blockIdx.x * 64;

    const __nv_bfloat16* qh = g_qh + (size_t)bh * SL * DK;
    const __nv_bfloat16* ql = g_ql + (size_t)bh * SL * DK;
    const __nv_bfloat16* kh = g_kh + (size_t)bh * SL * DK;
    const __nv_bfloat16* kl = g_kl + (size_t)bh * SL * DK;
    const __nv_bfloat16* vh = g_vh + (size_t)bh * SL * DK;
    const __nv_bfloat16* vl = g_vl + (size_t)bh * SL * DK;

    // ldmatrix lane offsets (bf16 elem units)
    const uint32_t a_loff = (uint32_t)((lane & 15) * ST + (lane >> 4) * 8);
    const uint32_t b_loff = (uint32_t)(((lane >> 4) * 8 + (lane & 7)) * ST +
                                       ((lane >> 3) & 1) * 8);
    const uint32_t vt_loff = (uint32_t)((((lane >> 3) & 1) * 8 + (lane & 7)) * ST +
                                        (lane >> 4) * 8);

    const uint32_t sQh = (uint32_t)__cvta_generic_to_shared(Qh);
    const uint32_t sQl = (uint32_t)__cvta_generic_to_shared(Ql);
    const uint32_t sKh = (uint32_t)__cvta_generic_to_shared(Kh);
    const uint32_t sKl = (uint32_t)__cvta_generic_to_shared(Kl);
    const uint32_t sVh = (uint32_t)__cvta_generic_to_shared(Vh);
    const uint32_t sVl = (uint32_t)__cvta_generic_to_shared(Vl);

    // Load Q tiles (hi/lo): 64x64 = 512 float4 each, 4/thread
#pragma unroll
    for (int r = 0; r < 4; r++) {
        int idx = tid + r * 128;
        int row = idx >> 3;
        int c8  = (idx & 7) * 8;
        *(float4*)(Qh + row * ST + c8) =
            *(const float4*)(qh + (size_t)(q0 + row) * DK + c8);
        *(float4*)(Ql + row * ST + c8) =
            *(const float4*)(ql + (size_t)(q0 + row) * DK + c8);
    }

    float m0v = -1e30f, m1v = -1e30f, l0 = 0.f, l1 = 0.f;
    float ctx[8][4];
#pragma unroll
    for (int j = 0; j < 8; j++)
#pragma unroll
        for (int q = 0; q < 4; q++) ctx[j][q] = 0.f;

    for (int t = 0; t < SL / 64; t++) {
        const int n0 = t * 64;
        // K and V tiles (hi/lo): 64x64 = 512 float4 each, 4/thread each pair
#pragma unroll
        for (int r = 0; r < 4; r++) {
            int idx = tid + r * 128;
            int row = idx >> 3;
            int c8  = (idx & 7) * 8;
            *(float4*)(Kh + row * ST + c8) =
                *(const float4*)(kh + (size_t)(n0 + row) * DK + c8);
            *(float4*)(Kl + row * ST + c8) =
                *(const float4*)(kl + (size_t)(n0 + row) * DK + c8);
            *(float4*)(Vh + row * ST + c8) =
                *(const float4*)(vh + (size_t)(n0 + row) * DK + c8);
            *(float4*)(Vl + row * ST + c8) =
                *(const float4*)(vl + (size_t)(n0 + row) * DK + c8);
        }
        __syncthreads();

        // S = Q K^T (split, 3 mma per fragment pair), accum fp32
        float s[8][4];
#pragma unroll
        for (int j = 0; j < 8; j++)
#pragma unroll
            for (int q = 0; q < 4; q++) s[j][q] = 0.f;

#pragma unroll
        for (int ks = 0; ks < 4; ks++) {
            const uint32_t kb = ks * 16;
            uint32_t ah[4], al[4];
            {
                uint32_t off = (uint32_t)(wid * 16 * ST) + kb + a_loff;
                ldsm_x4(ah, sQh + off * 2);
                ldsm_x4(al, sQl + off * 2);
            }
#pragma unroll
            for (int jp = 0; jp < 4; jp++) {
                uint32_t off = (uint32_t)(16 * jp * ST) + kb + b_loff;
                uint32_t bhr[4], blr[4];
                ldsm_x4(bhr, sKh + off * 2);
                ldsm_x4(blr, sKl + off * 2);
                mma16816(s[2 * jp],     ah, bhr);
                mma16816(s[2 * jp],     al, bhr);
                mma16816(s[2 * jp],     ah, blr);
                mma16816(s[2 * jp + 1], ah, bhr + 2);
                mma16816(s[2 * jp + 1], al, bhr + 2);
                mma16816(s[2 * jp + 1], ah, blr + 2);
            }
        }

        // Online softmax in log2 domain (rows lane>>2 and +8)
        float mx0 = -1e30f, mx1 = -1e30f;
#pragma unroll
        for (int j = 0; j < 8; j++) {
            s[j][0] *= SCALE; s[j][1] *= SCALE;
            s[j][2] *= SCALE; s[j][3] *= SCALE;
            mx0 = fmaxf(mx0, fmaxf(s[j][0], s[j][1]));
            mx1 = fmaxf(mx1, fmaxf(s[j][2], s[j][3]));
        }
        mx0 = fmaxf(mx0, __shfl_xor_sync(0xffffffffu, mx0, 1));
        mx0 = fmaxf(mx0, __shfl_xor_sync(0xffffffffu, mx0, 2));
        mx1 = fmaxf(mx1, __shfl_xor_sync(0xffffffffu, mx1, 1));
        mx1 = fmaxf(mx1, __shfl_xor_sync(0xffffffffu, mx1, 2));

        float mn0 = fmaxf(m0v, mx0), mn1 = fmaxf(m1v, mx1);
        float al0 = exp2a(m0v - mn0), al1 = exp2a(m1v - mn1);
        float rs0 = 0.f, rs1 = 0.f;
#pragma unroll
        for (int j = 0; j < 8; j++) {
            s[j][0] = exp2a(s[j][0] - mn0);
            s[j][1] = exp2a(s[j][1] - mn0);
            s[j][2] = exp2a(s[j][2] - mn1);
            s[j][3] = exp2a(s[j][3] - mn1);
            rs0 += s[j][0] + s[j][1];
            rs1 += s[j][2] + s[j][3];
        }
        rs0 += __shfl_xor_sync(0xffffffffu, rs0, 1);
        rs0 += __shfl_xor_sync(0xffffffffu, rs0, 2);
        rs1 += __shfl_xor_sync(0xffffffffu, rs1, 1);
        rs1 += __shfl_xor_sync(0xffffffffu, rs1, 2);

        l0 = l0 * al0 + rs0;  m0v = mn0;
        l1 = l1 * al1 + rs1;  m1v = mn1;
#pragma unroll
        for (int j = 0; j < 8; j++) {
            ctx[j][0] *= al0; ctx[j][1] *= al0;
            ctx[j][2] *= al1; ctx[j][3] *= al1;
        }

        // ctx += P V: P split per-kk in registers; V frags via ldmatrix.trans
#pragma unroll
        for (int kk = 0; kk < 4; kk++) {
            const uint32_t kb = kk * 16;
            uint32_t ph[4], pl[4];
            split2(s[2 * kk][0],     s[2 * kk][1],     ph[0], pl[0]);
            split2(s[2 * kk][2],     s[2 * kk][3],     ph[1], pl[1]);
            split2(s[2 * kk + 1][0], s[2 * kk + 1][1], ph[2], pl[2]);
            split2(s[2 * kk + 1][2], s[2 * kk + 1][3], ph[3], pl[3]);
#pragma unroll
            for (int jp = 0; jp < 4; jp++) {
                uint32_t off = (uint32_t)(kb * ST) + 16 * jp + vt_loff;
                uint32_t bhr[4], blr[4];
                ldsm_x4_t(bhr, sVh + off * 2);
                ldsm_x4_t(blr, sVl + off * 2);
                mma16816(ctx[2 * jp],     ph, bhr);
                mma16816(ctx[2 * jp],     pl, bhr);
                mma16816(ctx[2 * jp],     ph, blr);
                mma16816(ctx[2 * jp + 1], ph, bhr + 2);
                mma16816(ctx[2 * jp + 1], pl, bhr + 2);
                mma16816(ctx[2 * jp + 1], ph, blr + 2);
            }
        }
        __syncthreads();
    }

    // Epilogue
    const int b_idx = bh / NH;
    const int h     = bh % NH;
    const float inv0 = 1.0f / l0, inv1 = 1.0f / l1;
    const int r0 = q0 + wid * 16 + (lane >> 2);
#pragma unroll
    for (int j = 0; j < 8; j++) {
        int d = 8 * j + (lane & 3) * 2;
        float* o0 = out + ((size_t)b_idx * SL + r0) * DM + h * DK + d;
        float* o1 = o0 + 8 * DM;
        *(float2*)o0 = make_float2(ctx[j][0] * inv0, ctx[j][1] * inv0);
        *(float2*)o1 = make_float2(ctx[j][2] * inv1, ctx[j][3] * inv1);
    }
}

// ---------------------------------------------------------------------------
extern "C" void kernel_launch(void* const* d_in, const int* in_sizes, int n_in,
                              void* d_out, int out_size)
{
    const float* query = (const float*)d_in[0];
    const float* key_  = (const float*)d_in[1];
    const float* value = (const float*)d_in[2];
    const float* W_Q   = (const float*)d_in[3];
    const float* b_Q   = (const float*)d_in[4];
    const float* W_K   = (const float*)d_in[5];
    const float* b_K   = (const float*)d_in[6];
    const float* W_V   = (const float*)d_in[7];
    const float* b_V   = (const float*)d_in[8];
    float* out = (float*)d_out;

    {
        dim3 g((MROWS * DM / 4) / 256, 3);
        convert_x_kernel<<<g, 256>>>(query, key_, value);
    }
    {
        dim3 g(DM / 32, DM / 32, 3);
        convert_w_kernel<<<g, dim3(32, 8)>>>(W_Q, W_K, W_V);
    }
    {
        const int smem = 4 * 128 * ST * 2;   // 73728 B
        cudaFuncSetAttribute(qkv_proj_mma_kernel,
                             cudaFuncAttributeMaxDynamicSharedMemorySize, smem);
        dim3 g(MROWS / 128, DM / 128, 3);
        qkv_proj_mma_kernel<<<g, 256, smem>>>(b_Q, b_K, b_V);
    }
    {
        const int smem = 6 * 64 * ST * 2;    // 55296 B
        cudaFuncSetAttribute(attn_mma_kernel,
                             cudaFuncAttributeMaxDynamicSharedMemorySize, smem);
        dim3 g(SL / 64, BH);
        attn_mma_kernel<<<g, 128, smem>>>(out);
    }
}

// round 8
// speedup vs baseline: 3.3898x; 1.0242x over previous
#include <cuda_runtime.h>
#include <cuda_bf16.h>
#include <math.h>
#include <stdint.h>

#define NB 4
#define NH 12
#define SL 2048
#define DK 64
#define DM 768
#define BH (NB*NH)
#define MROWS (NB*SL)          // 8192
#define ST 72                  // smem row stride in bf16 elems (144B)
#define NTILE (SL/64)          // 32

// ---------------------------------------------------------------------------
// Device scratch (static; no allocation)
// ---------------------------------------------------------------------------
__device__ __nv_bfloat16 g_xh[3][(size_t)MROWS * DM];
__device__ __nv_bfloat16 g_xl[3][(size_t)MROWS * DM];
__device__ __nv_bfloat16 g_wth[3][DM * DM];   // W^T (n,k), hi
__device__ __nv_bfloat16 g_wtl[3][DM * DM];   // W^T (n,k), lo

__device__ __nv_bfloat16 g_qh[(size_t)BH * SL * DK];
__device__ __nv_bfloat16 g_ql[(size_t)BH * SL * DK];
__device__ __nv_bfloat16 g_kh[(size_t)BH * SL * DK];
__device__ __nv_bfloat16 g_kl[(size_t)BH * SL * DK];
__device__ __nv_bfloat16 g_vh[(size_t)BH * SL * DK];
__device__ __nv_bfloat16 g_vl[(size_t)BH * SL * DK];

// ---------------------------------------------------------------------------
// Helpers
// ---------------------------------------------------------------------------
__device__ __forceinline__ void mma16816(float* c, const uint32_t* a,
                                         const uint32_t* b) {
    asm volatile(
        "mma.sync.aligned.m16n8k16.row.col.f32.bf16.bf16.f32 "
        "{%0,%1,%2,%3}, {%4,%5,%6,%7}, {%8,%9}, {%0,%1,%2,%3};\n"
        : "+f"(c[0]), "+f"(c[1]), "+f"(c[2]), "+f"(c[3])
        : "r"(a[0]), "r"(a[1]), "r"(a[2]), "r"(a[3]), "r"(b[0]), "r"(b[1]));
}

__device__ __forceinline__ void ldsm_x4(uint32_t* r, uint32_t addr) {
    asm volatile(
        "ldmatrix.sync.aligned.m8n8.x4.shared.b16 {%0,%1,%2,%3}, [%4];"
        : "=r"(r[0]), "=r"(r[1]), "=r"(r[2]), "=r"(r[3]) : "r"(addr));
}

__device__ __forceinline__ void ldsm_x4_t(uint32_t* r, uint32_t addr) {
    asm volatile(
        "ldmatrix.sync.aligned.m8n8.x4.trans.shared.b16 {%0,%1,%2,%3}, [%4];"
        : "=r"(r[0]), "=r"(r[1]), "=r"(r[2]), "=r"(r[3]) : "r"(addr));
}

__device__ __forceinline__ void cp16(uint32_t d, const void* s) {
    asm volatile("cp.async.ca.shared.global [%0], [%1], 16;" :: "r"(d), "l"(s));
}
#define CP_COMMIT() asm volatile("cp.async.commit_group;" ::: "memory")
#define CP_WAIT0()  asm volatile("cp.async.wait_group 0;" ::: "memory")

// FFMA-pipe exp2 (no MUFU): degree-6 poly on [0,1) + exponent-bit scaling.
__device__ __forceinline__ float exp2a(float x) {
    x = fmaxf(x, -80.f);
    float xi = floorf(x);
    float f = x - xi;
    float p = 1.53533e-4f;
    p = fmaf(p, f, 1.33989e-3f);
    p = fmaf(p, f, 9.61844e-3f);
    p = fmaf(p, f, 5.55033e-2f);
    p = fmaf(p, f, 2.40226e-1f);
    p = fmaf(p, f, 6.93147e-1f);
    p = fmaf(p, f, 1.0f);
    return p * __int_as_float(((int)xi + 127) << 23);
}

__device__ __forceinline__ void split2(float a, float b, uint32_t& h, uint32_t& l) {
    __nv_bfloat162 H = __floats2bfloat162_rn(a, b);
    float ra = a - __bfloat162float(H.x);
    float rb = b - __bfloat162float(H.y);
    __nv_bfloat162 L = __floats2bfloat162_rn(ra, rb);
    h = *(uint32_t*)&H;
    l = *(uint32_t*)&L;
}

// ---------------------------------------------------------------------------
// Conversion: X -> (hi, lo) bf16 split.
// ---------------------------------------------------------------------------
__global__ __launch_bounds__(256) void convert_x_kernel(
    const float* __restrict__ q, const float* __restrict__ k,
    const float* __restrict__ v)
{
    const int sel = blockIdx.y;
    const float* src = (sel == 0) ? q : (sel == 1) ? k : v;
    __nv_bfloat16* xh = g_xh[sel];
    __nv_bfloat16* xl = g_xl[sel];

    size_t idx = (size_t)blockIdx.x * blockDim.x + threadIdx.x;  // float4 index
    float4 x = ((const float4*)src)[idx];
    float vv[4] = {x.x, x.y, x.z, x.w};
    uint32_t h[2], l[2];
    split2(vv[0], vv[1], h[0], l[0]);
    split2(vv[2], vv[3], h[1], l[1]);
    ((uint32_t*)xh)[idx * 2 + 0] = h[0];
    ((uint32_t*)xh)[idx * 2 + 1] = h[1];
    ((uint32_t*)xl)[idx * 2 + 0] = l[0];
    ((uint32_t*)xl)[idx * 2 + 1] = l[1];
}

// ---------------------------------------------------------------------------
// Conversion: W[k][n] -> W^T[n][k] (hi, lo) bf16.
// ---------------------------------------------------------------------------
__global__ void convert_w_kernel(const float* __restrict__ Wq,
                                 const float* __restrict__ Wk,
                                 const float* __restrict__ Wv)
{
    __shared__ float t[32][33];
    const int sel = blockIdx.z;
    const float* W = (sel == 0) ? Wq : (sel == 1) ? Wk : Wv;
    const int k0 = blockIdx.x * 32;
    const int n0 = blockIdx.y * 32;
    const int tx = threadIdx.x, ty = threadIdx.y;

#pragma unroll
    for (int r = 0; r < 4; r++)
        t[ty + 8 * r][tx] = W[(size_t)(k0 + ty + 8 * r) * DM + n0 + tx];
    __syncthreads();

#pragma unroll
    for (int r = 0; r < 4; r++) {
        float v = t[tx][ty + 8 * r];
        __nv_bfloat16 h = __float2bfloat16_rn(v);
        __nv_bfloat16 l = __float2bfloat16_rn(v - __bfloat162float(h));
        size_t o = (size_t)(n0 + ty + 8 * r) * DM + k0 + tx;
        g_wth[sel][o] = h;
        g_wtl[sel][o] = l;
    }
}

// ---------------------------------------------------------------------------
// QKV projection via mma.sync bf16 split-precision (unchanged from R7).
// grid (64, 6, 3), 256 thr (8 warps: 2x4, warp tile 64x32).
// ---------------------------------------------------------------------------
__global__ __launch_bounds__(256) void qkv_proj_mma_kernel(
    const float* __restrict__ bq, const float* __restrict__ bk,
    const float* __restrict__ bv)
{
    extern __shared__ __nv_bfloat16 sm[];
    __nv_bfloat16* Xh = sm;                 // [128][ST]
    __nv_bfloat16* Xl = sm + 128 * ST;
    __nv_bfloat16* Wh = sm + 2 * 128 * ST;
    __nv_bfloat16* Wl = sm + 3 * 128 * ST;

    const int tid  = threadIdx.x;
    const int lane = tid & 31, wid = tid >> 5;
    const int wm = wid >> 2, wn = wid & 3;
    const int m0 = blockIdx.x * 128;
    const int n0 = blockIdx.y * 128;
    const int sel = blockIdx.z;

    const __nv_bfloat16* Agh = g_xh[sel];
    const __nv_bfloat16* Agl = g_xl[sel];
    const __nv_bfloat16* Bgh = g_wth[sel];
    const __nv_bfloat16* Bgl = g_wtl[sel];
    const float* bias = (sel == 0) ? bq : (sel == 1) ? bk : bv;
    __nv_bfloat16* dh = (sel == 0) ? g_qh : (sel == 1) ? g_kh : g_vh;
    __nv_bfloat16* dl = (sel == 0) ? g_ql : (sel == 1) ? g_kl : g_vl;

    const uint32_t a_loff = (uint32_t)((lane & 15) * ST + (lane >> 4) * 8);
    const uint32_t b_loff = (uint32_t)(((lane >> 4) * 8 + (lane & 7)) * ST +
                                       ((lane >> 3) & 1) * 8);

    float acc[4][4][4];
#pragma unroll
    for (int i = 0; i < 4; i++)
#pragma unroll
        for (int j = 0; j < 4; j++)
#pragma unroll
            for (int q = 0; q < 4; q++) acc[i][j][q] = 0.f;

    const uint32_t sXh = (uint32_t)__cvta_generic_to_shared(Xh);
    const uint32_t sXl = (uint32_t)__cvta_generic_to_shared(Xl);
    const uint32_t sWh = (uint32_t)__cvta_generic_to_shared(Wh);
    const uint32_t sWl = (uint32_t)__cvta_generic_to_shared(Wl);

    for (int ch = 0; ch < DM / 64; ch++) {
        const int k0 = ch * 64;
#pragma unroll
        for (int r = 0; r < 4; r++) {
            int idx = tid + r * 256;
            int row = idx >> 3;
            int c8  = (idx & 7) * 8;
            *(float4*)(Xh + row * ST + c8) =
                *(const float4*)(Agh + (size_t)(m0 + row) * DM + k0 + c8);
            *(float4*)(Xl + row * ST + c8) =
                *(const float4*)(Agl + (size_t)(m0 + row) * DM + k0 + c8);
            *(float4*)(Wh + row * ST + c8) =
                *(const float4*)(Bgh + (size_t)(n0 + row) * DM + k0 + c8);
            *(float4*)(Wl + row * ST + c8) =
                *(const float4*)(Bgl + (size_t)(n0 + row) * DM + k0 + c8);
        }
        __syncthreads();

#pragma unroll
        for (int ks = 0; ks < 4; ks++) {
            const uint32_t kb = ks * 16;
            uint32_t ah[4][4], al[4][4];
#pragma unroll
            for (int i = 0; i < 4; i++) {
                uint32_t off = (uint32_t)((wm * 64 + 16 * i) * ST) + kb + a_loff;
                ldsm_x4(ah[i], sXh + off * 2);
                ldsm_x4(al[i], sXl + off * 2);
            }
#pragma unroll
            for (int jp = 0; jp < 2; jp++) {
                uint32_t off = (uint32_t)((wn * 32 + 16 * jp) * ST) + kb + b_loff;
                uint32_t bh[4], bl[4];
                ldsm_x4(bh, sWh + off * 2);
                ldsm_x4(bl, sWl + off * 2);
#pragma unroll
                for (int i = 0; i < 4; i++) {
                    mma16816(acc[i][2 * jp],     ah[i], bh);
                    mma16816(acc[i][2 * jp],     al[i], bh);
                    mma16816(acc[i][2 * jp],     ah[i], bl);
                    mma16816(acc[i][2 * jp + 1], ah[i], bh + 2);
                    mma16816(acc[i][2 * jp + 1], al[i], bh + 2);
                    mma16816(acc[i][2 * jp + 1], ah[i], bl + 2);
                }
            }
        }
        __syncthreads();
    }

    // Epilogue: bias, split to hi/lo bf16, head-split store
#pragma unroll
    for (int i = 0; i < 4; i++) {
#pragma unroll
        for (int j = 0; j < 4; j++) {
            int col = n0 + wn * 32 + 8 * j + (lane & 3) * 2;
            float b0 = bias[col], b1 = bias[col + 1];
            int h = col >> 6, c = col & 63;
#pragma unroll
            for (int half = 0; half < 2; half++) {
                int row = m0 + wm * 64 + 16 * i + (lane >> 2) + 8 * half;
                int bidx = row >> 11;
                int s    = row & (SL - 1);
                float v0 = acc[i][j][2 * half + 0] + b0;
                float v1 = acc[i][j][2 * half + 1] + b1;
                uint32_t hh, ll;
                split2(v0, v1, hh, ll);
                size_t off = (((size_t)bidx * NH + h) * SL + s) * DK + c;
                *(uint32_t*)(dh + off) = hh;
                *(uint32_t*)(dl + off) = ll;
            }
        }
    }
}

// ---------------------------------------------------------------------------
// Flash attention: mma.sync + ldmatrix + cp.async double buffering.
// grid (SL/128 = 16, 48), 128 thr (4 warps x 32 q-rows). Br = 128, Bc = 64.
// 2 CTAs/SM; K/V tiles prefetched one tile ahead.
// ---------------------------------------------------------------------------
#define SCALE 0.1803368801111137f    // (1/8) * log2(e)
#define KVBUF (4 * 64 * ST)          // one stage: Kh,Kl,Vh,Vl (elems)

__global__ __launch_bounds__(128, 2) void attn_mma_kernel(float* __restrict__ out)
{
    extern __shared__ __nv_bfloat16 sm[];
    __nv_bfloat16* Qh = sm;                    // [128][ST]
    __nv_bfloat16* Ql = sm + 128 * ST;
    __nv_bfloat16* KV = sm + 2 * 128 * ST;     // 2 stages x (Kh,Kl,Vh,Vl)[64][ST]

    const int tid  = threadIdx.x;
    const int lane = tid & 31, wid = tid >> 5;
    const int bh = blockIdx.y;
    const int q0 = blockIdx.x * 128;

    const __nv_bfloat16* qh = g_qh + (size_t)bh * SL * DK;
    const __nv_bfloat16* ql = g_ql + (size_t)bh * SL * DK;
    const __nv_bfloat16* kh = g_kh + (size_t)bh * SL * DK;
    const __nv_bfloat16* kl = g_kl + (size_t)bh * SL * DK;
    const __nv_bfloat16* vh = g_vh + (size_t)bh * SL * DK;
    const __nv_bfloat16* vl = g_vl + (size_t)bh * SL * DK;

    // ldmatrix lane offsets (bf16 elem units)
    const uint32_t a_loff = (uint32_t)((lane & 15) * ST + (lane >> 4) * 8);
    const uint32_t b_loff = (uint32_t)(((lane >> 4) * 8 + (lane & 7)) * ST +
                                       ((lane >> 3) & 1) * 8);
    const uint32_t vt_loff = (uint32_t)((((lane >> 3) & 1) * 8 + (lane & 7)) * ST +
                                        (lane >> 4) * 8);

    const uint32_t sQh = (uint32_t)__cvta_generic_to_shared(Qh);
    const uint32_t sQl = (uint32_t)__cvta_generic_to_shared(Ql);
    const uint32_t sKV = (uint32_t)__cvta_generic_to_shared(KV);

    // Load Q tiles (hi/lo): 128x64 = 1024 float4 each, 8/thread
#pragma unroll
    for (int r = 0; r < 8; r++) {
        int idx = tid + r * 128;
        int row = idx >> 3;
        int c8  = (idx & 7) * 8;
        *(float4*)(Qh + row * ST + c8) =
            *(const float4*)(qh + (size_t)(q0 + row) * DK + c8);
        *(float4*)(Ql + row * ST + c8) =
            *(const float4*)(ql + (size_t)(q0 + row) * DK + c8);
    }

    // cp.async issue for one K/V stage (16 x 16B per thread)
    auto issue_tile = [&](int t, int buf) {
        const int n0 = t * 64;
        const uint32_t dbase = sKV + (uint32_t)(buf * KVBUF * 2);
#pragma unroll
        for (int r = 0; r < 4; r++) {
            int idx = tid + r * 128;
            int row = idx >> 3;
            int c8  = (idx & 7) * 8;
            uint32_t drow = dbase + (uint32_t)((row * ST + c8) * 2);
            size_t go = (size_t)(n0 + row) * DK + c8;
            cp16(drow,                     kh + go);
            cp16(drow + 64 * ST * 2,       kl + go);
            cp16(drow + 2 * 64 * ST * 2,   vh + go);
            cp16(drow + 3 * 64 * ST * 2,   vl + go);
        }
    };

    issue_tile(0, 0);
    CP_COMMIT();

    float mv[2][2], lv[2][2], ctx[2][8][4];
#pragma unroll
    for (int mi = 0; mi < 2; mi++) {
        mv[mi][0] = mv[mi][1] = -1e30f;
        lv[mi][0] = lv[mi][1] = 0.f;
#pragma unroll
        for (int j = 0; j < 8; j++)
#pragma unroll
            for (int q = 0; q < 4; q++) ctx[mi][j][q] = 0.f;
    }

    for (int t = 0; t < NTILE; t++) {
        CP_WAIT0();
        __syncthreads();
        if (t + 1 < NTILE) {
            issue_tile(t + 1, (t + 1) & 1);
            CP_COMMIT();
        }

        const uint32_t sb  = sKV + (uint32_t)((t & 1) * KVBUF * 2);
        const uint32_t sKh = sb;
        const uint32_t sKl = sb + 64 * ST * 2;
        const uint32_t sVh = sb + 2 * 64 * ST * 2;
        const uint32_t sVl = sb + 3 * 64 * ST * 2;

        // S = Q K^T (split, 3 mma per frag pair), accum fp32
        float s[2][8][4];
#pragma unroll
        for (int mi = 0; mi < 2; mi++)
#pragma unroll
            for (int j = 0; j < 8; j++)
#pragma unroll
                for (int q = 0; q < 4; q++) s[mi][j][q] = 0.f;

#pragma unroll
        for (int ks = 0; ks < 4; ks++) {
            const uint32_t kb = ks * 16;
            uint32_t ah[2][4], al[2][4];
#pragma unroll
            for (int mi = 0; mi < 2; mi++) {
                uint32_t off = (uint32_t)((wid * 32 + mi * 16) * ST) + kb + a_loff;
                ldsm_x4(ah[mi], sQh + off * 2);
                ldsm_x4(al[mi], sQl + off * 2);
            }
#pragma unroll
            for (int jp = 0; jp < 4; jp++) {
                uint32_t off = (uint32_t)(16 * jp * ST) + kb + b_loff;
                uint32_t bhr[4], blr[4];
                ldsm_x4(bhr, sKh + off * 2);
                ldsm_x4(blr, sKl + off * 2);
#pragma unroll
                for (int mi = 0; mi < 2; mi++) {
                    mma16816(s[mi][2 * jp],     ah[mi], bhr);
                    mma16816(s[mi][2 * jp],     al[mi], bhr);
                    mma16816(s[mi][2 * jp],     ah[mi], blr);
                    mma16816(s[mi][2 * jp + 1], ah[mi], bhr + 2);
                    mma16816(s[mi][2 * jp + 1], al[mi], bhr + 2);
                    mma16816(s[mi][2 * jp + 1], ah[mi], blr + 2);
                }
            }
        }

        // Online softmax in log2 domain (per mi: rows lane>>2 and +8)
#pragma unroll
        for (int mi = 0; mi < 2; mi++) {
            float mx0 = -1e30f, mx1 = -1e30f;
#pragma unroll
            for (int j = 0; j < 8; j++) {
                s[mi][j][0] *= SCALE; s[mi][j][1] *= SCALE;
                s[mi][j][2] *= SCALE; s[mi][j][3] *= SCALE;
                mx0 = fmaxf(mx0, fmaxf(s[mi][j][0], s[mi][j][1]));
                mx1 = fmaxf(mx1, fmaxf(s[mi][j][2], s[mi][j][3]));
            }
            mx0 = fmaxf(mx0, __shfl_xor_sync(0xffffffffu, mx0, 1));
            mx0 = fmaxf(mx0, __shfl_xor_sync(0xffffffffu, mx0, 2));
            mx1 = fmaxf(mx1, __shfl_xor_sync(0xffffffffu, mx1, 1));
            mx1 = fmaxf(mx1, __shfl_xor_sync(0xffffffffu, mx1, 2));

            float mn0 = fmaxf(mv[mi][0], mx0), mn1 = fmaxf(mv[mi][1], mx1);
            float al0 = exp2a(mv[mi][0] - mn0), al1 = exp2a(mv[mi][1] - mn1);
            float rs0 = 0.f, rs1 = 0.f;
#pragma unroll
            for (int j = 0; j < 8; j++) {
                s[mi][j][0] = exp2a(s[mi][j][0] - mn0);
                s[mi][j][1] = exp2a(s[mi][j][1] - mn0);
                s[mi][j][2] = exp2a(s[mi][j][2] - mn1);
                s[mi][j][3] = exp2a(s[mi][j][3] - mn1);
                rs0 += s[mi][j][0] + s[mi][j][1];
                rs1 += s[mi][j][2] + s[mi][j][3];
            }
            rs0 += __shfl_xor_sync(0xffffffffu, rs0, 1);
            rs0 += __shfl_xor_sync(0xffffffffu, rs0, 2);
            rs1 += __shfl_xor_sync(0xffffffffu, rs1, 1);
            rs1 += __shfl_xor_sync(0xffffffffu, rs1, 2);

            lv[mi][0] = lv[mi][0] * al0 + rs0;  mv[mi][0] = mn0;
            lv[mi][1] = lv[mi][1] * al1 + rs1;  mv[mi][1] = mn1;
#pragma unroll
            for (int j = 0; j < 8; j++) {
                ctx[mi][j][0] *= al0; ctx[mi][j][1] *= al0;
                ctx[mi][j][2] *= al1; ctx[mi][j][3] *= al1;
            }
        }

        // ctx += P V: P split per-kk in registers; V frags via ldmatrix.trans
        // (V fragments shared across both mi halves)
#pragma unroll
        for (int kk = 0; kk < 4; kk++) {
            const uint32_t kb = kk * 16;
            uint32_t ph[2][4], pl[2][4];
#pragma unroll
            for (int mi = 0; mi < 2; mi++) {
                split2(s[mi][2 * kk][0],     s[mi][2 * kk][1],     ph[mi][0], pl[mi][0]);
                split2(s[mi][2 * kk][2],     s[mi][2 * kk][3],     ph[mi][1], pl[mi][1]);
                split2(s[mi][2 * kk + 1][0], s[mi][2 * kk + 1][1], ph[mi][2], pl[mi][2]);
                split2(s[mi][2 * kk + 1][2], s[mi][2 * kk + 1][3], ph[mi][3], pl[mi][3]);
            }
#pragma unroll
            for (int jp = 0; jp < 4; jp++) {
                uint32_t off = (uint32_t)(kb * ST) + 16 * jp + vt_loff;
                uint32_t bhr[4], blr[4];
                ldsm_x4_t(bhr, sVh + off * 2);
                ldsm_x4_t(blr, sVl + off * 2);
#pragma unroll
                for (int mi = 0; mi < 2; mi++) {
                    mma16816(ctx[mi][2 * jp],     ph[mi], bhr);
                    mma16816(ctx[mi][2 * jp],     pl[mi], bhr);
                    mma16816(ctx[mi][2 * jp],     ph[mi], blr);
                    mma16816(ctx[mi][2 * jp + 1], ph[mi], bhr + 2);
                    mma16816(ctx[mi][2 * jp + 1], pl[mi], bhr + 2);
                    mma16816(ctx[mi][2 * jp + 1], ph[mi], blr + 2);
                }
            }
        }
    }

    // Epilogue
    const int b_idx = bh / NH;
    const int h     = bh % NH;
#pragma unroll
    for (int mi = 0; mi < 2; mi++) {
        const float inv0 = 1.0f / lv[mi][0], inv1 = 1.0f / lv[mi][1];
        const int r0 = q0 + wid * 32 + mi * 16 + (lane >> 2);
#pragma unroll
        for (int j = 0; j < 8; j++) {
            int d = 8 * j + (lane & 3) * 2;
            float* o0 = out + ((size_t)b_idx * SL + r0) * DM + h * DK + d;
            float* o1 = o0 + 8 * DM;
            *(float2*)o0 = make_float2(ctx[mi][j][0] * inv0, ctx[mi][j][1] * inv0);
            *(float2*)o1 = make_float2(ctx[mi][j][2] * inv1, ctx[mi][j][3] * inv1);
        }
    }
}

// ---------------------------------------------------------------------------
extern "C" void kernel_launch(void* const* d_in, const int* in_sizes, int n_in,
                              void* d_out, int out_size)
{
    const float* query = (const float*)d_in[0];
    const float* key_  = (const float*)d_in[1];
    const float* value = (const float*)d_in[2];
    const float* W_Q   = (const float*)d_in[3];
    const float* b_Q   = (const float*)d_in[4];
    const float* W_K   = (const float*)d_in[5];
    const float* b_K   = (const float*)d_in[6];
    const float* W_V   = (const float*)d_in[7];
    const float* b_V   = (const float*)d_in[8];
    float* out = (float*)d_out;

    {
        dim3 g((MROWS * DM / 4) / 256, 3);
        convert_x_kernel<<<g, 256>>>(query, key_, value);
    }
    {
        dim3 g(DM / 32, DM / 32, 3);
        convert_w_kernel<<<g, dim3(32, 8)>>>(W_Q, W_K, W_V);
    }
    {
        const int smem = 4 * 128 * ST * 2;   // 73728 B
        cudaFuncSetAttribute(qkv_proj_mma_kernel,
                             cudaFuncAttributeMaxDynamicSharedMemorySize, smem);
        dim3 g(MROWS / 128, DM / 128, 3);
        qkv_proj_mma_kernel<<<g, 256, smem>>>(b_Q, b_K, b_V);
    }
    {
        const int smem = (2 * 128 * ST + 2 * KVBUF) * 2;   // 110592 B
        cudaFuncSetAttribute(attn_mma_kernel,
                             cudaFuncAttributeMaxDynamicSharedMemorySize, smem);
        dim3 g(SL / 128, BH);
        attn_mma_kernel<<<g, 128, smem>>>(out);
    }
}